// round 1
// baseline (speedup 1.0000x reference)
#include <cuda_runtime.h>
#include <cuda_bf16.h>
#include <math.h>

// ---------------- Problem constants ----------------
#define BATCH   2
#define SEQ_T   1024
#define D_IN    2048
#define NH      32
#define NKV     8
#define HD      128
#define L_PREV  1024
#define L_FULL  2048
#define GROUP   (NH / NKV)          // 4
#define SCALE   0.08838834764831845f // 1/sqrt(128)

#define MROWS   (BATCH * SEQ_T)     // 2048
#define QCOLS   (NH * HD)           // 4096
#define KVCOLS  (NKV * HD)          // 1024

// ---------------- Scratch (static device globals; no allocation) ----------------
__device__ float g_qraw[MROWS * QCOLS];   // 32 MB
__device__ float g_kraw[MROWS * KVCOLS];  //  8 MB
__device__ float g_vraw[MROWS * KVCOLS];  //  8 MB
__device__ float g_qrot[MROWS * QCOLS];   // 32 MB  (B,H,T,HD)
__device__ float g_ctx [MROWS * QCOLS];   // 32 MB  (B,T,H*HD)

// =================================================================
// GEMM  C[M,N] = A[M,K] * B[N,K]^T   (both K-contiguous, "NT")
// BM=BN=128, BK=16, 256 threads, 8x8 per thread (split 4+4 mapping)
// =================================================================
__global__ __launch_bounds__(256)
void gemm_nt(const float* __restrict__ A, const float* __restrict__ B,
             float* __restrict__ C, int M, int N, int K)
{
    __shared__ float As[16][132];
    __shared__ float Bs[16][132];

    const int tid = threadIdx.x;
    const int tx = tid & 15;          // N dimension
    const int ty = tid >> 4;          // M dimension
    const int m0 = blockIdx.y * 128;
    const int n0 = blockIdx.x * 128;

    float acc[8][8];
#pragma unroll
    for (int i = 0; i < 8; i++)
#pragma unroll
        for (int j = 0; j < 8; j++) acc[i][j] = 0.f;

    for (int k0 = 0; k0 < K; k0 += 16) {
        // global -> shared (transposed to k-major)
#pragma unroll
        for (int it = 0; it < 2; it++) {
            int f   = tid + it * 256;         // 0..511 float4 slots
            int row = f >> 2;                 // 0..127
            int c4  = (f & 3) * 4;            // 0,4,8,12
            float4 av = *(const float4*)&A[(size_t)(m0 + row) * K + k0 + c4];
            float4 bv = *(const float4*)&B[(size_t)(n0 + row) * K + k0 + c4];
            As[c4 + 0][row] = av.x; As[c4 + 1][row] = av.y;
            As[c4 + 2][row] = av.z; As[c4 + 3][row] = av.w;
            Bs[c4 + 0][row] = bv.x; Bs[c4 + 1][row] = bv.y;
            Bs[c4 + 2][row] = bv.z; Bs[c4 + 3][row] = bv.w;
        }
        __syncthreads();

#pragma unroll
        for (int k = 0; k < 16; k++) {
            float a[8], b[8];
            *(float4*)&a[0] = *(float4*)&As[k][ty * 4];
            *(float4*)&a[4] = *(float4*)&As[k][64 + ty * 4];
            *(float4*)&b[0] = *(float4*)&Bs[k][tx * 4];
            *(float4*)&b[4] = *(float4*)&Bs[k][64 + tx * 4];
#pragma unroll
            for (int i = 0; i < 8; i++)
#pragma unroll
                for (int j = 0; j < 8; j++)
                    acc[i][j] += a[i] * b[j];
        }
        __syncthreads();
    }

#pragma unroll
    for (int i = 0; i < 8; i++) {
        int rm = (i < 4) ? (ty * 4 + i) : (64 + ty * 4 + (i - 4));
        float4 c0 = make_float4(acc[i][0], acc[i][1], acc[i][2], acc[i][3]);
        float4 c1 = make_float4(acc[i][4], acc[i][5], acc[i][6], acc[i][7]);
        *(float4*)&C[(size_t)(m0 + rm) * N + n0 + tx * 4]      = c0;
        *(float4*)&C[(size_t)(m0 + rm) * N + n0 + 64 + tx * 4] = c1;
    }
}

// =================================================================
// Q post-process: RMSNorm + RoPE + scale, layout (B,H,T,HD)
// one block (128 threads) per (b,t,h)
// =================================================================
__global__ __launch_bounds__(128)
void qpost(const float* __restrict__ qraw, const float* __restrict__ cosb,
           const float* __restrict__ sinb, const float* __restrict__ qw,
           float* __restrict__ qrot)
{
    const int blk = blockIdx.x;          // (b*T+t)*NH + h
    const int h  = blk & (NH - 1);
    const int bt = blk >> 5;             // b*T + t
    const int t  = bt & (SEQ_T - 1);
    const int b  = bt >> 10;
    const int d  = threadIdx.x;

    float v = qraw[(size_t)bt * QCOLS + h * HD + d];

    __shared__ float red[4];
    __shared__ float xs[HD];
    float ss = v * v;
#pragma unroll
    for (int o = 16; o > 0; o >>= 1) ss += __shfl_xor_sync(0xffffffffu, ss, o);
    if ((d & 31) == 0) red[d >> 5] = ss;
    __syncthreads();
    float tot = red[0] + red[1] + red[2] + red[3];
    float inv = rsqrtf(tot * (1.f / HD) + 1e-6f);
    float xn  = v * inv * qw[d];
    xs[d] = xn;
    __syncthreads();
    float other = xs[d ^ 64];
    float rot   = (d < 64) ? -other : other;
    int pos = L_PREV + t;
    float c = cosb[pos * HD + d];
    float s = sinb[pos * HD + d];
    float o = (xn * c + rot * s) * SCALE;
    qrot[(((size_t)b * NH + h) * SEQ_T + t) * HD + d] = o;
}

// =================================================================
// K/V post-process: K = RMSNorm+RoPE -> full_k[.., L_PREV+t, :]
//                   V = copy        -> full_v[.., L_PREV+t, :]
// one block (128 threads) per (b,t,hkv)
// =================================================================
__global__ __launch_bounds__(128)
void kvpost(const float* __restrict__ kraw, const float* __restrict__ vraw,
            const float* __restrict__ cosb, const float* __restrict__ sinb,
            const float* __restrict__ kw,
            float* __restrict__ fullk, float* __restrict__ fullv)
{
    const int blk = blockIdx.x;          // (b*T+t)*NKV + h
    const int h  = blk & (NKV - 1);
    const int bt = blk >> 3;
    const int t  = bt & (SEQ_T - 1);
    const int b  = bt >> 10;
    const int d  = threadIdx.x;

    float kv = kraw[(size_t)bt * KVCOLS + h * HD + d];
    float vv = vraw[(size_t)bt * KVCOLS + h * HD + d];

    __shared__ float red[4];
    __shared__ float xs[HD];
    float ss = kv * kv;
#pragma unroll
    for (int o = 16; o > 0; o >>= 1) ss += __shfl_xor_sync(0xffffffffu, ss, o);
    if ((d & 31) == 0) red[d >> 5] = ss;
    __syncthreads();
    float tot = red[0] + red[1] + red[2] + red[3];
    float inv = rsqrtf(tot * (1.f / HD) + 1e-6f);
    float xn  = kv * inv * kw[d];
    xs[d] = xn;
    __syncthreads();
    float other = xs[d ^ 64];
    float rot   = (d < 64) ? -other : other;
    int pos = L_PREV + t;
    float c = cosb[pos * HD + d];
    float s = sinb[pos * HD + d];
    float ko = xn * c + rot * s;

    size_t dst = (((size_t)b * NKV + h) * L_FULL + (L_PREV + t)) * HD + d;
    fullk[dst] = ko;
    fullv[dst] = vv;
}

// =================================================================
// Copy prev_k / prev_v into the [0, L_PREV) region of full_k/full_v
// =================================================================
__global__ __launch_bounds__(256)
void prev_copy(const float4* __restrict__ pk, const float4* __restrict__ pv,
               float4* __restrict__ outk, float4* __restrict__ outv)
{
    int i = blockIdx.x * blockDim.x + threadIdx.x;   // 0 .. 524287
    int chunk = i >> 15;                             // (b*NKV + h)
    int r = i & 32767;                               // within 1024*128/4
    outk[(size_t)chunk * 65536 + r] = pk[i];
    outv[(size_t)chunk * 65536 + r] = pv[i];
}

// =================================================================
// Flash attention. grid (T/64, H, B), 128 threads.
// Online softmax; only the last key tile is masked (j_local > q_local).
// =================================================================
#define ATTN_SMEM_FLOATS (3 * 64 * 132 + 64 * 65)
#define ATTN_SMEM_BYTES  (ATTN_SMEM_FLOATS * 4)

__global__ __launch_bounds__(128)
void attn_kernel(const float* __restrict__ q, const float* __restrict__ kfull,
                 const float* __restrict__ vfull, float* __restrict__ ctx)
{
    const int bx = blockIdx.x;
    const int h  = blockIdx.y;
    const int b  = blockIdx.z;
    const int t0 = bx * 64;
    const int hkv = h >> 2;

    extern __shared__ float sm[];
    float* Qs = sm;                       // 64 x 132
    float* Ks = Qs + 64 * 132;            // 64 x 132
    float* Vs = Ks + 64 * 132;            // 64 x 132
    float* Ps = Vs + 64 * 132;            // 64 x 65

    const int tid = threadIdx.x;
    const int tx = tid & 7;               // key-lane (8) / dim-lane
    const int ty = tid >> 3;              // 0..15: 4 query rows each

    // load Q tile (64 x 128)
    const float* qbase = q + ((size_t)(b * NH + h) * SEQ_T + t0) * HD;
    for (int f = tid; f < 64 * 32; f += 128) {
        int r = f >> 5, c4 = (f & 31) * 4;
        *(float4*)&Qs[r * 132 + c4] = *(const float4*)&qbase[r * HD + c4];
    }

    float m[4], l[4];
    float4 acc[4][4];
#pragma unroll
    for (int qi = 0; qi < 4; qi++) {
        m[qi] = -1e30f; l[qi] = 0.f;
#pragma unroll
        for (int di = 0; di < 4; di++) acc[qi][di] = make_float4(0.f, 0.f, 0.f, 0.f);
    }

    const float* kb = kfull + (size_t)(b * NKV + hkv) * L_FULL * HD;
    const float* vb = vfull + (size_t)(b * NKV + hkv) * L_FULL * HD;

    const int ntiles = 17 + bx;           // keys up to 1024 + t0 + 63 inclusive

    for (int tile = 0; tile < ntiles; tile++) {
        __syncthreads();                  // Ks/Vs/Ps free; also orders Q load (first iter)
        int j0 = tile * 64;
        for (int f = tid; f < 64 * 32; f += 128) {
            int r = f >> 5, c4 = (f & 31) * 4;
            *(float4*)&Ks[r * 132 + c4] = *(const float4*)&kb[(size_t)(j0 + r) * HD + c4];
            *(float4*)&Vs[r * 132 + c4] = *(const float4*)&vb[(size_t)(j0 + r) * HD + c4];
        }
        __syncthreads();

        // S = Q K^T   (q already scaled); s[qi][kj] covers key j = kj*8 + tx
        float s[4][8];
#pragma unroll
        for (int qi = 0; qi < 4; qi++)
#pragma unroll
            for (int kj = 0; kj < 8; kj++) s[qi][kj] = 0.f;

        for (int d4 = 0; d4 < HD; d4 += 4) {
            float4 qv[4];
#pragma unroll
            for (int qi = 0; qi < 4; qi++)
                qv[qi] = *(float4*)&Qs[(ty * 4 + qi) * 132 + d4];
#pragma unroll
            for (int kj = 0; kj < 8; kj++) {
                float4 kv = *(float4*)&Ks[(kj * 8 + tx) * 132 + d4];
#pragma unroll
                for (int qi = 0; qi < 4; qi++) {
                    s[qi][kj] += qv[qi].x * kv.x + qv[qi].y * kv.y
                               + qv[qi].z * kv.z + qv[qi].w * kv.w;
                }
            }
        }

        const bool last = (tile == ntiles - 1);
        if (last) {
#pragma unroll
            for (int qi = 0; qi < 4; qi++) {
                int qrow = ty * 4 + qi;
#pragma unroll
                for (int kj = 0; kj < 8; kj++) {
                    if (kj * 8 + tx > qrow) s[qi][kj] = -1e30f;
                }
            }
        }

        // online softmax
#pragma unroll
        for (int qi = 0; qi < 4; qi++) {
            float mx = s[qi][0];
#pragma unroll
            for (int kj = 1; kj < 8; kj++) mx = fmaxf(mx, s[qi][kj]);
            mx = fmaxf(mx, __shfl_xor_sync(0xffffffffu, mx, 1));
            mx = fmaxf(mx, __shfl_xor_sync(0xffffffffu, mx, 2));
            mx = fmaxf(mx, __shfl_xor_sync(0xffffffffu, mx, 4));
            float nm   = fmaxf(m[qi], mx);
            float corr = __expf(m[qi] - nm);
            float rs = 0.f;
#pragma unroll
            for (int kj = 0; kj < 8; kj++) {
                float p = __expf(s[qi][kj] - nm);
                Ps[(ty * 4 + qi) * 65 + kj * 8 + tx] = p;
                rs += p;
            }
            rs += __shfl_xor_sync(0xffffffffu, rs, 1);
            rs += __shfl_xor_sync(0xffffffffu, rs, 2);
            rs += __shfl_xor_sync(0xffffffffu, rs, 4);
            l[qi] = l[qi] * corr + rs;
            m[qi] = nm;
#pragma unroll
            for (int di = 0; di < 4; di++) {
                acc[qi][di].x *= corr; acc[qi][di].y *= corr;
                acc[qi][di].z *= corr; acc[qi][di].w *= corr;
            }
        }
        __syncthreads();

        // PV: out[q][d] += P[q][j] * V[j][d], thread dims d = di*32 + tx*4 + {0..3}
        for (int j = 0; j < 64; j++) {
            float p[4];
#pragma unroll
            for (int qi = 0; qi < 4; qi++) p[qi] = Ps[(ty * 4 + qi) * 65 + j];
            float4 vv[4];
#pragma unroll
            for (int di = 0; di < 4; di++)
                vv[di] = *(float4*)&Vs[j * 132 + di * 32 + tx * 4];
#pragma unroll
            for (int qi = 0; qi < 4; qi++)
#pragma unroll
                for (int di = 0; di < 4; di++) {
                    acc[qi][di].x += p[qi] * vv[di].x;
                    acc[qi][di].y += p[qi] * vv[di].y;
                    acc[qi][di].z += p[qi] * vv[di].z;
                    acc[qi][di].w += p[qi] * vv[di].w;
                }
        }
    }

    // epilogue: ctx[b, t, h*HD + d]
#pragma unroll
    for (int qi = 0; qi < 4; qi++) {
        float invl = 1.f / l[qi];
        int t = t0 + ty * 4 + qi;
        size_t base = ((size_t)b * SEQ_T + t) * QCOLS + h * HD;
#pragma unroll
        for (int di = 0; di < 4; di++) {
            float4 o = acc[qi][di];
            o.x *= invl; o.y *= invl; o.z *= invl; o.w *= invl;
            *(float4*)&g_ctx[base + di * 32 + tx * 4] = o;
        }
    }
}

// =================================================================
// Launch
// =================================================================
extern "C" void kernel_launch(void* const* d_in, const int* in_sizes, int n_in,
                              void* d_out, int out_size)
{
    const float* x      = (const float*)d_in[0];
    // d_in[1] attn_mask (causal, reconstructed analytically) — unused
    const float* cosb   = (const float*)d_in[2];
    const float* sinb   = (const float*)d_in[3];
    // d_in[4] position_ids == L_PREV + t — unused
    const float* prev_k = (const float*)d_in[5];
    const float* prev_v = (const float*)d_in[6];
    const float* Wq     = (const float*)d_in[7];
    const float* Wk     = (const float*)d_in[8];
    const float* Wv     = (const float*)d_in[9];
    const float* Wo     = (const float*)d_in[10];
    const float* qw     = (const float*)d_in[11];
    const float* kw     = (const float*)d_in[12];

    float* out   = (float*)d_out;                               // (B,T,D_IN)
    float* fullk = out + (size_t)MROWS * D_IN;                  // (B,NKV,L_FULL,HD)
    float* fullv = fullk + (size_t)BATCH * NKV * L_FULL * HD;   // same size

    float *qraw, *kraw, *vraw, *qrot, *ctx;
    cudaGetSymbolAddress((void**)&qraw, g_qraw);
    cudaGetSymbolAddress((void**)&kraw, g_kraw);
    cudaGetSymbolAddress((void**)&vraw, g_vraw);
    cudaGetSymbolAddress((void**)&qrot, g_qrot);
    cudaGetSymbolAddress((void**)&ctx,  g_ctx);

    cudaFuncSetAttribute(attn_kernel, cudaFuncAttributeMaxDynamicSharedMemorySize,
                         ATTN_SMEM_BYTES);

    // 1) projections
    gemm_nt<<<dim3(QCOLS / 128, MROWS / 128), 256>>>(x, Wq, qraw, MROWS, QCOLS, D_IN);
    gemm_nt<<<dim3(KVCOLS / 128, MROWS / 128), 256>>>(x, Wk, kraw, MROWS, KVCOLS, D_IN);
    gemm_nt<<<dim3(KVCOLS / 128, MROWS / 128), 256>>>(x, Wv, vraw, MROWS, KVCOLS, D_IN);

    // 2) norm + rope + cache assembly
    qpost<<<MROWS * NH, 128>>>(qraw, cosb, sinb, qw, qrot);
    kvpost<<<MROWS * NKV, 128>>>(kraw, vraw, cosb, sinb, kw, fullk, fullv);
    prev_copy<<<2048, 256>>>((const float4*)prev_k, (const float4*)prev_v,
                             (float4*)fullk, (float4*)fullv);

    // 3) attention -> ctx
    attn_kernel<<<dim3(SEQ_T / 64, NH, BATCH), 128, ATTN_SMEM_BYTES>>>(qrot, fullk, fullv, ctx);

    // 4) output projection
    gemm_nt<<<dim3(D_IN / 128, MROWS / 128), 256>>>(ctx, Wo, out, MROWS, D_IN, QCOLS);
}

// round 4
// speedup vs baseline: 1.2220x; 1.2220x over previous
#include <cuda_runtime.h>
#include <cuda_bf16.h>
#include <cstdint>
#include <math.h>

// ---------------- Problem constants ----------------
#define BATCH   2
#define SEQ_T   1024
#define D_IN    2048
#define NH      32
#define NKV     8
#define HD      128
#define L_PREV  1024
#define L_FULL  2048
#define SCALE   0.08838834764831845f // 1/sqrt(128)

#define MROWS   (BATCH * SEQ_T)     // 2048
#define QCOLS   (NH * HD)           // 4096
#define KVCOLS  (NKV * HD)          // 1024

// ---------------- Scratch (static device globals; no allocation) ----------------
__device__ float g_qraw[MROWS * QCOLS];   // 32 MB
__device__ float g_kraw[MROWS * KVCOLS];  //  8 MB
__device__ float g_vraw[MROWS * KVCOLS];  //  8 MB
__device__ float g_qrot[MROWS * QCOLS];   // 32 MB  (B,H,T,HD)
__device__ float g_ctx [MROWS * QCOLS];   // 32 MB  (B,T,H*HD)

__device__ __forceinline__ uint32_t smem_u32(const void* p) {
    uint32_t a;
    asm("{ .reg .u64 t; cvta.to.shared.u64 t, %1; cvt.u32.u64 %0, t; }"
        : "=r"(a) : "l"(p));
    return a;
}

// =================================================================
// mma.sync bf16 GEMM  C[M,N] = A[M,K] * B[N,K]^T  (fp32 in/out, bf16x3)
// Tile 128x128, K-chunk 32 fp32 -> K'=96 bf16 (hi|lo|hi vs hi|hi|lo).
// 256 threads = 8 warps, warp tile 64x32 (2x4 warp grid).
// SMEM rows padded to 104 bf16 (208B) -> conflict-free ldmatrix.
// =================================================================
#define GPAD 104
#define GEMM_SMEM_BYTES (2 * 128 * GPAD * 2)   // 53248

__device__ __forceinline__ void ldm_x4(uint32_t addr, uint32_t r[4]) {
    asm volatile("ldmatrix.sync.aligned.m8n8.x4.shared.b16 {%0,%1,%2,%3}, [%4];"
                 : "=r"(r[0]), "=r"(r[1]), "=r"(r[2]), "=r"(r[3]) : "r"(addr));
}

__device__ __forceinline__ void mma16816(float d[4], const uint32_t a[4],
                                         uint32_t b0, uint32_t b1) {
    asm volatile(
        "mma.sync.aligned.m16n8k16.row.col.f32.bf16.bf16.f32 "
        "{%0,%1,%2,%3}, {%4,%5,%6,%7}, {%8,%9}, {%0,%1,%2,%3};"
        : "+f"(d[0]), "+f"(d[1]), "+f"(d[2]), "+f"(d[3])
        : "r"(a[0]), "r"(a[1]), "r"(a[2]), "r"(a[3]), "r"(b0), "r"(b1));
}

// fp32x4 -> (hi 4xbf16, lo 4xbf16)
__device__ __forceinline__ void hilo4(float4 v, uint2& hp, uint2& lp) {
    __nv_bfloat162 h01 = __floats2bfloat162_rn(v.x, v.y);
    __nv_bfloat162 h23 = __floats2bfloat162_rn(v.z, v.w);
    float2 f01 = __bfloat1622float2(h01);
    float2 f23 = __bfloat1622float2(h23);
    __nv_bfloat162 l01 = __floats2bfloat162_rn(v.x - f01.x, v.y - f01.y);
    __nv_bfloat162 l23 = __floats2bfloat162_rn(v.z - f23.x, v.w - f23.y);
    hp = make_uint2(*(uint32_t*)&h01, *(uint32_t*)&h23);
    lp = make_uint2(*(uint32_t*)&l01, *(uint32_t*)&l23);
}

__global__ __launch_bounds__(256)
void gemm_mma(const float* __restrict__ A, const float* __restrict__ Bm,
              float* __restrict__ C, int M, int N, int K)
{
    extern __shared__ __align__(16) __nv_bfloat16 smg[];
    __nv_bfloat16* As = smg;                 // 128 x 104
    __nv_bfloat16* Bs = smg + 128 * GPAD;    // 128 x 104

    const int tid = threadIdx.x;
    const int lane = tid & 31, wid = tid >> 5;
    const int m0 = blockIdx.y * 128, n0 = blockIdx.x * 128;
    const int m_w = (wid & 1) * 64, n_w = (wid >> 1) * 32;

    const uint32_t asB = smem_u32(As), bsB = smem_u32(Bs);

    // ldmatrix per-lane source coords
    const int tA = lane >> 3;
    const int a_m = (lane & 7) + ((tA & 1) << 3);
    const int a_k = (tA >> 1) << 3;
    const int b_n = (lane & 7) + ((tA >> 1) << 3);
    const int b_k = (tA & 1) << 3;

    float acc[4][4][4];
#pragma unroll
    for (int mi = 0; mi < 4; mi++)
#pragma unroll
        for (int ni = 0; ni < 4; ni++)
#pragma unroll
            for (int r = 0; r < 4; r++) acc[mi][ni][r] = 0.f;

    for (int k0 = 0; k0 < K; k0 += 32) {
        __syncthreads();
        // load 128x32 fp32 of A and B, convert, store split segments
#pragma unroll
        for (int it = 0; it < 4; it++) {
            int f = tid + (it << 8);          // 0..1023
            int row = f >> 3;                 // 0..127
            int c4 = (f & 7) << 2;            // 0..28
            float4 va = *(const float4*)(A + (size_t)(m0 + row) * K + k0 + c4);
            float4 vb = *(const float4*)(Bm + (size_t)(n0 + row) * K + k0 + c4);
            uint2 hp, lp;
            hilo4(va, hp, lp);
            *(uint2*)(As + row * GPAD + c4)      = hp;   // A hi (term 1)
            *(uint2*)(As + row * GPAD + c4 + 32) = lp;   // A lo (term 2)
            *(uint2*)(As + row * GPAD + c4 + 64) = hp;   // A hi (term 3)
            hilo4(vb, hp, lp);
            *(uint2*)(Bs + row * GPAD + c4)      = hp;   // B hi
            *(uint2*)(Bs + row * GPAD + c4 + 32) = hp;   // B hi
            *(uint2*)(Bs + row * GPAD + c4 + 64) = lp;   // B lo
        }
        __syncthreads();

#pragma unroll
        for (int ks = 0; ks < 6; ks++) {
            uint32_t a[4][4];
#pragma unroll
            for (int mi = 0; mi < 4; mi++) {
                uint32_t addr = asB +
                    ((m_w + mi * 16 + a_m) * GPAD + ks * 16 + a_k) * 2;
                ldm_x4(addr, a[mi]);
            }
            uint32_t b[2][4];
#pragma unroll
            for (int pi = 0; pi < 2; pi++) {
                uint32_t addr = bsB +
                    ((n_w + pi * 16 + b_n) * GPAD + ks * 16 + b_k) * 2;
                ldm_x4(addr, b[pi]);
            }
#pragma unroll
            for (int mi = 0; mi < 4; mi++) {
#pragma unroll
                for (int ni = 0; ni < 4; ni++) {
                    mma16816(acc[mi][ni], a[mi],
                             b[ni >> 1][(ni & 1) * 2],
                             b[ni >> 1][(ni & 1) * 2 + 1]);
                }
            }
        }
    }

    // epilogue: c0,c1 -> (row g, col q,q+1); c2,c3 -> (row g+8)
    const int g = lane >> 2, q = (lane & 3) << 1;
#pragma unroll
    for (int mi = 0; mi < 4; mi++) {
#pragma unroll
        for (int ni = 0; ni < 4; ni++) {
            int row = m0 + m_w + mi * 16 + g;
            int col = n0 + n_w + ni * 8 + q;
            *(float2*)(C + (size_t)row * N + col) =
                make_float2(acc[mi][ni][0], acc[mi][ni][1]);
            *(float2*)(C + (size_t)(row + 8) * N + col) =
                make_float2(acc[mi][ni][2], acc[mi][ni][3]);
        }
    }
}

// =================================================================
// Q post-process: RMSNorm + RoPE + scale, layout (B,H,T,HD)
// =================================================================
__global__ __launch_bounds__(128)
void qpost(const float* __restrict__ qraw, const float* __restrict__ cosb,
           const float* __restrict__ sinb, const float* __restrict__ qw,
           float* __restrict__ qrot)
{
    const int blk = blockIdx.x;          // (b*T+t)*NH + h
    const int h  = blk & (NH - 1);
    const int bt = blk >> 5;             // b*T + t
    const int t  = bt & (SEQ_T - 1);
    const int b  = bt >> 10;
    const int d  = threadIdx.x;

    float v = qraw[(size_t)bt * QCOLS + h * HD + d];

    __shared__ float red[4];
    __shared__ float xs[HD];
    float ss = v * v;
#pragma unroll
    for (int o = 16; o > 0; o >>= 1) ss += __shfl_xor_sync(0xffffffffu, ss, o);
    if ((d & 31) == 0) red[d >> 5] = ss;
    __syncthreads();
    float tot = red[0] + red[1] + red[2] + red[3];
    float inv = rsqrtf(tot * (1.f / HD) + 1e-6f);
    float xn  = v * inv * qw[d];
    xs[d] = xn;
    __syncthreads();
    float other = xs[d ^ 64];
    float rot   = (d < 64) ? -other : other;
    int pos = L_PREV + t;
    float c = cosb[pos * HD + d];
    float s = sinb[pos * HD + d];
    float o = (xn * c + rot * s) * SCALE;
    qrot[(((size_t)b * NH + h) * SEQ_T + t) * HD + d] = o;
}

// =================================================================
// K/V post-process
// =================================================================
__global__ __launch_bounds__(128)
void kvpost(const float* __restrict__ kraw, const float* __restrict__ vraw,
            const float* __restrict__ cosb, const float* __restrict__ sinb,
            const float* __restrict__ kw,
            float* __restrict__ fullk, float* __restrict__ fullv)
{
    const int blk = blockIdx.x;          // (b*T+t)*NKV + h
    const int h  = blk & (NKV - 1);
    const int bt = blk >> 3;
    const int t  = bt & (SEQ_T - 1);
    const int b  = bt >> 10;
    const int d  = threadIdx.x;

    float kv = kraw[(size_t)bt * KVCOLS + h * HD + d];
    float vv = vraw[(size_t)bt * KVCOLS + h * HD + d];

    __shared__ float red[4];
    __shared__ float xs[HD];
    float ss = kv * kv;
#pragma unroll
    for (int o = 16; o > 0; o >>= 1) ss += __shfl_xor_sync(0xffffffffu, ss, o);
    if ((d & 31) == 0) red[d >> 5] = ss;
    __syncthreads();
    float tot = red[0] + red[1] + red[2] + red[3];
    float inv = rsqrtf(tot * (1.f / HD) + 1e-6f);
    float xn  = kv * inv * kw[d];
    xs[d] = xn;
    __syncthreads();
    float other = xs[d ^ 64];
    float rot   = (d < 64) ? -other : other;
    int pos = L_PREV + t;
    float c = cosb[pos * HD + d];
    float s = sinb[pos * HD + d];
    float ko = xn * c + rot * s;

    size_t dst = (((size_t)b * NKV + h) * L_FULL + (L_PREV + t)) * HD + d;
    fullk[dst] = ko;
    fullv[dst] = vv;
}

// =================================================================
// Copy prev_k / prev_v into [0, L_PREV) of full_k/full_v
// =================================================================
__global__ __launch_bounds__(256)
void prev_copy(const float4* __restrict__ pk, const float4* __restrict__ pv,
               float4* __restrict__ outk, float4* __restrict__ outv)
{
    int i = blockIdx.x * blockDim.x + threadIdx.x;   // 0 .. 524287
    int chunk = i >> 15;                             // (b*NKV + h)
    int r = i & 32767;
    outk[(size_t)chunk * 65536 + r] = pk[i];
    outv[(size_t)chunk * 65536 + r] = pv[i];
}

// =================================================================
// Flash attention (scalar). grid (T/64, H, B), 256 threads (8 warps).
// Each thread: 2 query rows (ty=tid>>3 in 0..31), key-lane tx=tid&7.
// =================================================================
#define ATTN_SMEM_FLOATS (3 * 64 * 132 + 64 * 65)
#define ATTN_SMEM_BYTES  (ATTN_SMEM_FLOATS * 4)

__global__ __launch_bounds__(256)
void attn_kernel(const float* __restrict__ q, const float* __restrict__ kfull,
                 const float* __restrict__ vfull, float* __restrict__ ctx)
{
    const int bx = blockIdx.x;
    const int h  = blockIdx.y;
    const int b  = blockIdx.z;
    const int t0 = bx * 64;
    const int hkv = h >> 2;

    extern __shared__ float smf[];
    float* Qs = smf;                      // 64 x 132
    float* Ks = Qs + 64 * 132;            // 64 x 132
    float* Vs = Ks + 64 * 132;            // 64 x 132
    float* Ps = Vs + 64 * 132;            // 64 x 65

    const int tid = threadIdx.x;
    const int tx = tid & 7;               // key/dim lane
    const int ty = tid >> 3;              // 0..31: 2 query rows each

    const float* qbase = q + ((size_t)(b * NH + h) * SEQ_T + t0) * HD;
    for (int f = tid; f < 64 * 32; f += 256) {
        int r = f >> 5, c4 = (f & 31) * 4;
        *(float4*)&Qs[r * 132 + c4] = *(const float4*)&qbase[r * HD + c4];
    }

    float m[2], l[2];
    float4 acc[2][4];
#pragma unroll
    for (int qi = 0; qi < 2; qi++) {
        m[qi] = -1e30f; l[qi] = 0.f;
#pragma unroll
        for (int di = 0; di < 4; di++) acc[qi][di] = make_float4(0.f, 0.f, 0.f, 0.f);
    }

    const float* kb = kfull + (size_t)(b * NKV + hkv) * L_FULL * HD;
    const float* vb = vfull + (size_t)(b * NKV + hkv) * L_FULL * HD;

    const int ntiles = 17 + bx;

    for (int tile = 0; tile < ntiles; tile++) {
        __syncthreads();
        int j0 = tile * 64;
        for (int f = tid; f < 64 * 32; f += 256) {
            int r = f >> 5, c4 = (f & 31) * 4;
            *(float4*)&Ks[r * 132 + c4] = *(const float4*)&kb[(size_t)(j0 + r) * HD + c4];
            *(float4*)&Vs[r * 132 + c4] = *(const float4*)&vb[(size_t)(j0 + r) * HD + c4];
        }
        __syncthreads();

        float s[2][8];
#pragma unroll
        for (int qi = 0; qi < 2; qi++)
#pragma unroll
            for (int kj = 0; kj < 8; kj++) s[qi][kj] = 0.f;

        for (int d4 = 0; d4 < HD; d4 += 4) {
            float4 qv[2];
#pragma unroll
            for (int qi = 0; qi < 2; qi++)
                qv[qi] = *(float4*)&Qs[(ty * 2 + qi) * 132 + d4];
#pragma unroll
            for (int kj = 0; kj < 8; kj++) {
                float4 kv = *(float4*)&Ks[(kj * 8 + tx) * 132 + d4];
#pragma unroll
                for (int qi = 0; qi < 2; qi++) {
                    s[qi][kj] += qv[qi].x * kv.x + qv[qi].y * kv.y
                               + qv[qi].z * kv.z + qv[qi].w * kv.w;
                }
            }
        }

        const bool last = (tile == ntiles - 1);
        if (last) {
#pragma unroll
            for (int qi = 0; qi < 2; qi++) {
                int qrow = ty * 2 + qi;
#pragma unroll
                for (int kj = 0; kj < 8; kj++) {
                    if (kj * 8 + tx > qrow) s[qi][kj] = -1e30f;
                }
            }
        }

#pragma unroll
        for (int qi = 0; qi < 2; qi++) {
            float mx = s[qi][0];
#pragma unroll
            for (int kj = 1; kj < 8; kj++) mx = fmaxf(mx, s[qi][kj]);
            mx = fmaxf(mx, __shfl_xor_sync(0xffffffffu, mx, 1));
            mx = fmaxf(mx, __shfl_xor_sync(0xffffffffu, mx, 2));
            mx = fmaxf(mx, __shfl_xor_sync(0xffffffffu, mx, 4));
            float nm   = fmaxf(m[qi], mx);
            float corr = __expf(m[qi] - nm);
            float rs = 0.f;
#pragma unroll
            for (int kj = 0; kj < 8; kj++) {
                float p = __expf(s[qi][kj] - nm);
                Ps[(ty * 2 + qi) * 65 + kj * 8 + tx] = p;
                rs += p;
            }
            rs += __shfl_xor_sync(0xffffffffu, rs, 1);
            rs += __shfl_xor_sync(0xffffffffu, rs, 2);
            rs += __shfl_xor_sync(0xffffffffu, rs, 4);
            l[qi] = l[qi] * corr + rs;
            m[qi] = nm;
#pragma unroll
            for (int di = 0; di < 4; di++) {
                acc[qi][di].x *= corr; acc[qi][di].y *= corr;
                acc[qi][di].z *= corr; acc[qi][di].w *= corr;
            }
        }
        __syncthreads();

        for (int j = 0; j < 64; j++) {
            float p[2];
#pragma unroll
            for (int qi = 0; qi < 2; qi++) p[qi] = Ps[(ty * 2 + qi) * 65 + j];
            float4 vv[4];
#pragma unroll
            for (int di = 0; di < 4; di++)
                vv[di] = *(float4*)&Vs[j * 132 + di * 32 + tx * 4];
#pragma unroll
            for (int qi = 0; qi < 2; qi++)
#pragma unroll
                for (int di = 0; di < 4; di++) {
                    acc[qi][di].x += p[qi] * vv[di].x;
                    acc[qi][di].y += p[qi] * vv[di].y;
                    acc[qi][di].z += p[qi] * vv[di].z;
                    acc[qi][di].w += p[qi] * vv[di].w;
                }
        }
    }

#pragma unroll
    for (int qi = 0; qi < 2; qi++) {
        float invl = 1.f / l[qi];
        int t = t0 + ty * 2 + qi;
        size_t base = ((size_t)b * SEQ_T + t) * QCOLS + h * HD;
#pragma unroll
        for (int di = 0; di < 4; di++) {
            float4 o = acc[qi][di];
            o.x *= invl; o.y *= invl; o.z *= invl; o.w *= invl;
            *(float4*)&ctx[base + di * 32 + tx * 4] = o;
        }
    }
}

// =================================================================
// Launch
// =================================================================
extern "C" void kernel_launch(void* const* d_in, const int* in_sizes, int n_in,
                              void* d_out, int out_size)
{
    const float* x      = (const float*)d_in[0];
    const float* cosb   = (const float*)d_in[2];
    const float* sinb   = (const float*)d_in[3];
    const float* prev_k = (const float*)d_in[5];
    const float* prev_v = (const float*)d_in[6];
    const float* Wq     = (const float*)d_in[7];
    const float* Wk     = (const float*)d_in[8];
    const float* Wv     = (const float*)d_in[9];
    const float* Wo     = (const float*)d_in[10];
    const float* qw     = (const float*)d_in[11];
    const float* kw     = (const float*)d_in[12];

    float* out   = (float*)d_out;                               // (B,T,D_IN)
    float* fullk = out + (size_t)MROWS * D_IN;                  // (B,NKV,L_FULL,HD)
    float* fullv = fullk + (size_t)BATCH * NKV * L_FULL * HD;

    float *qraw, *kraw, *vraw, *qrot, *ctx;
    cudaGetSymbolAddress((void**)&qraw, g_qraw);
    cudaGetSymbolAddress((void**)&kraw, g_kraw);
    cudaGetSymbolAddress((void**)&vraw, g_vraw);
    cudaGetSymbolAddress((void**)&qrot, g_qrot);
    cudaGetSymbolAddress((void**)&ctx,  g_ctx);

    cudaFuncSetAttribute(attn_kernel, cudaFuncAttributeMaxDynamicSharedMemorySize,
                         ATTN_SMEM_BYTES);
    cudaFuncSetAttribute(gemm_mma, cudaFuncAttributeMaxDynamicSharedMemorySize,
                         GEMM_SMEM_BYTES);

    // 1) projections (mma.sync bf16x3)
    gemm_mma<<<dim3(QCOLS / 128, MROWS / 128), 256, GEMM_SMEM_BYTES>>>(x, Wq, qraw, MROWS, QCOLS, D_IN);
    gemm_mma<<<dim3(KVCOLS / 128, MROWS / 128), 256, GEMM_SMEM_BYTES>>>(x, Wk, kraw, MROWS, KVCOLS, D_IN);
    gemm_mma<<<dim3(KVCOLS / 128, MROWS / 128), 256, GEMM_SMEM_BYTES>>>(x, Wv, vraw, MROWS, KVCOLS, D_IN);

    // 2) norm + rope + cache assembly
    qpost<<<MROWS * NH, 128>>>(qraw, cosb, sinb, qw, qrot);
    kvpost<<<MROWS * NKV, 128>>>(kraw, vraw, cosb, sinb, kw, fullk, fullv);
    prev_copy<<<2048, 256>>>((const float4*)prev_k, (const float4*)prev_v,
                             (float4*)fullk, (float4*)fullv);

    // 3) attention -> ctx
    attn_kernel<<<dim3(SEQ_T / 64, NH, BATCH), 256, ATTN_SMEM_BYTES>>>(qrot, fullk, fullv, ctx);

    // 4) output projection (mma.sync bf16x3)
    gemm_mma<<<dim3(D_IN / 128, MROWS / 128), 256, GEMM_SMEM_BYTES>>>(ctx, Wo, out, MROWS, D_IN, QCOLS);
}

// round 5
// speedup vs baseline: 2.8226x; 2.3098x over previous
#include <cuda_runtime.h>
#include <cuda_bf16.h>
#include <cuda_fp16.h>
#include <cstdint>
#include <math.h>

// ---------------- Problem constants ----------------
#define BATCH   2
#define SEQ_T   1024
#define D_IN    2048
#define NH      32
#define NKV     8
#define HD      128
#define L_PREV  1024
#define L_FULL  2048
#define SCALE   0.08838834764831845f // 1/sqrt(128)

#define MROWS   (BATCH * SEQ_T)     // 2048
#define QCOLS   (NH * HD)           // 4096
#define KVCOLS  (NKV * HD)          // 1024

// ---------------- Scratch (static device globals; no allocation) ----------------
__device__ float g_qraw[MROWS * QCOLS];
__device__ float g_kraw[MROWS * KVCOLS];
__device__ float g_vraw[MROWS * KVCOLS];
__device__ float g_qrot[MROWS * QCOLS];          // (B,H,T,HD)
__device__ float g_ctx [MROWS * QCOLS];          // (B,T,H*HD)

// bf16 split-3 operand buffers
__device__ __nv_bfloat16 g_x3  [MROWS * 3 * D_IN];    // 24 MB
__device__ __nv_bfloat16 g_w3q [QCOLS * 3 * D_IN];    // 48 MB
__device__ __nv_bfloat16 g_w3k [KVCOLS * 3 * D_IN];   // 12 MB
__device__ __nv_bfloat16 g_w3v [KVCOLS * 3 * D_IN];   // 12 MB
__device__ __nv_bfloat16 g_w3o [D_IN * 3 * QCOLS];    // 48 MB
__device__ __nv_bfloat16 g_ctx3[MROWS * 3 * QCOLS];   // 48 MB

__device__ __forceinline__ uint32_t smem_u32(const void* p) {
    uint32_t a;
    asm("{ .reg .u64 t; cvta.to.shared.u64 t, %1; cvt.u32.u64 %0, t; }"
        : "=r"(a) : "l"(p));
    return a;
}

// fp32x4 -> (hi 4xbf16, lo 4xbf16)
__device__ __forceinline__ void hilo4(float4 v, uint2& hp, uint2& lp) {
    __nv_bfloat162 h01 = __floats2bfloat162_rn(v.x, v.y);
    __nv_bfloat162 h23 = __floats2bfloat162_rn(v.z, v.w);
    float2 f01 = __bfloat1622float2(h01);
    float2 f23 = __bfloat1622float2(h23);
    __nv_bfloat162 l01 = __floats2bfloat162_rn(v.x - f01.x, v.y - f01.y);
    __nv_bfloat162 l23 = __floats2bfloat162_rn(v.z - f23.x, v.w - f23.y);
    hp = make_uint2(*(uint32_t*)&h01, *(uint32_t*)&h23);
    lp = make_uint2(*(uint32_t*)&l01, *(uint32_t*)&l23);
}

// =================================================================
// split3: src[R][K] fp32 -> dst[R][3K] bf16.
// modeB=0: [hi|lo|hi]  (A operands);  modeB=1: [hi|hi|lo]  (B operands)
// =================================================================
__global__ __launch_bounds__(256)
void split3(const float4* __restrict__ src, __nv_bfloat16* __restrict__ dst,
            int K, int s4, int n4, int modeB)
{
    for (int idx = blockIdx.x * blockDim.x + threadIdx.x; idx < n4;
         idx += gridDim.x * blockDim.x) {
        int row = idx >> s4;
        int c4  = (idx - (row << s4)) << 2;
        float4 v = src[idx];
        uint2 hp, lp;
        hilo4(v, hp, lp);
        size_t base = (size_t)row * 3 * K + c4;
        *(uint2*)(dst + base)         = hp;
        *(uint2*)(dst + base + K)     = modeB ? hp : lp;
        *(uint2*)(dst + base + 2 * K) = modeB ? lp : hp;
    }
}

// =================================================================
// mma.sync helpers (validated mapping from round 4)
// =================================================================
__device__ __forceinline__ void ldm_x4(uint32_t addr, uint32_t r[4]) {
    asm volatile("ldmatrix.sync.aligned.m8n8.x4.shared.b16 {%0,%1,%2,%3}, [%4];"
                 : "=r"(r[0]), "=r"(r[1]), "=r"(r[2]), "=r"(r[3]) : "r"(addr));
}
__device__ __forceinline__ void ldm_x4_t(uint32_t addr, uint32_t r[4]) {
    asm volatile("ldmatrix.sync.aligned.m8n8.x4.trans.shared.b16 {%0,%1,%2,%3}, [%4];"
                 : "=r"(r[0]), "=r"(r[1]), "=r"(r[2]), "=r"(r[3]) : "r"(addr));
}
__device__ __forceinline__ void mma_bf16(float d[4], const uint32_t a[4],
                                         uint32_t b0, uint32_t b1) {
    asm volatile(
        "mma.sync.aligned.m16n8k16.row.col.f32.bf16.bf16.f32 "
        "{%0,%1,%2,%3}, {%4,%5,%6,%7}, {%8,%9}, {%0,%1,%2,%3};"
        : "+f"(d[0]), "+f"(d[1]), "+f"(d[2]), "+f"(d[3])
        : "r"(a[0]), "r"(a[1]), "r"(a[2]), "r"(a[3]), "r"(b0), "r"(b1));
}
__device__ __forceinline__ void mma_f16(float d[4], const uint32_t a[4],
                                        uint32_t b0, uint32_t b1) {
    asm volatile(
        "mma.sync.aligned.m16n8k16.row.col.f32.f16.f16.f32 "
        "{%0,%1,%2,%3}, {%4,%5,%6,%7}, {%8,%9}, {%0,%1,%2,%3};"
        : "+f"(d[0]), "+f"(d[1]), "+f"(d[2]), "+f"(d[3])
        : "r"(a[0]), "r"(a[1]), "r"(a[2]), "r"(a[3]), "r"(b0), "r"(b1));
}
__device__ __forceinline__ void cp16(uint32_t dst, const void* src) {
    asm volatile("cp.async.cg.shared.global [%0], [%1], 16;"
                 :: "r"(dst), "l"(src));
}
__device__ __forceinline__ void cp_commit() {
    asm volatile("cp.async.commit_group;");
}
__device__ __forceinline__ void cp_wait0() {
    asm volatile("cp.async.wait_group 0;");
}

// =================================================================
// bf16 GEMM  C[M,N] = A3[M,K3] * B3[N,K3]^T  (pre-split bf16 operands)
// 128x128 tile, BK=64, 2-stage cp.async double buffer, 256 threads.
// =================================================================
#define APITCH 72
#define GSTG   (128 * APITCH * 2)         // 18432 bytes per stage per matrix
#define GEMM_SMEM_BYTES (4 * GSTG)        // 73728

__global__ __launch_bounds__(256, 2)
void gemm_bf16(const __nv_bfloat16* __restrict__ A,
               const __nv_bfloat16* __restrict__ Bm,
               float* __restrict__ C, int N, int K3)
{
    extern __shared__ __align__(16) char smg[];
    const uint32_t sb = smem_u32(smg);

    const int tid = threadIdx.x;
    const int lane = tid & 31, wid = tid >> 5;
    const int m0 = blockIdx.y * 128, n0 = blockIdx.x * 128;
    const int m_w = (wid & 1) * 64, n_w = (wid >> 1) * 32;

    // ldmatrix per-lane source coords (validated round-4 mapping)
    const int tA = lane >> 3;
    const int a_m = (lane & 7) + ((tA & 1) << 3);
    const int a_k = (tA >> 1) << 3;
    const int b_n = (lane & 7) + ((tA >> 1) << 3);
    const int b_k = (tA & 1) << 3;

    float acc[4][4][4];
#pragma unroll
    for (int mi = 0; mi < 4; mi++)
#pragma unroll
        for (int ni = 0; ni < 4; ni++)
#pragma unroll
            for (int r = 0; r < 4; r++) acc[mi][ni][r] = 0.f;

    const int nkt = K3 >> 6;

    // stage loader: 64 bf16 columns from row-major K3-pitch operands
    auto load_stage = [&](int kt, int s) {
        const __nv_bfloat16* Ap = A + (size_t)m0 * K3 + kt * 64;
        const __nv_bfloat16* Bp = Bm + (size_t)n0 * K3 + kt * 64;
#pragma unroll
        for (int i = 0; i < 4; i++) {
            int f = tid + (i << 8);           // 0..1023
            int row = f >> 3;                 // 0..127
            int c = (f & 7) << 3;             // 0..56
            cp16(sb + s * GSTG + (row * APITCH + c) * 2,
                 Ap + (size_t)row * K3 + c);
            cp16(sb + 2 * GSTG + s * GSTG + (row * APITCH + c) * 2,
                 Bp + (size_t)row * K3 + c);
        }
    };

    load_stage(0, 0);
    cp_commit();

    for (int kt = 0; kt < nkt; kt++) {
        const int s = kt & 1;
        cp_wait0();
        __syncthreads();
        if (kt + 1 < nkt) { load_stage(kt + 1, s ^ 1); cp_commit(); }

        const uint32_t as = sb + s * GSTG;
        const uint32_t bs = sb + 2 * GSTG + s * GSTG;
#pragma unroll
        for (int ks = 0; ks < 4; ks++) {
            uint32_t a[4][4];
#pragma unroll
            for (int mi = 0; mi < 4; mi++)
                ldm_x4(as + ((m_w + mi * 16 + a_m) * APITCH + ks * 16 + a_k) * 2, a[mi]);
            uint32_t b[2][4];
#pragma unroll
            for (int pi = 0; pi < 2; pi++)
                ldm_x4(bs + ((n_w + pi * 16 + b_n) * APITCH + ks * 16 + b_k) * 2, b[pi]);
#pragma unroll
            for (int mi = 0; mi < 4; mi++)
#pragma unroll
                for (int ni = 0; ni < 4; ni++)
                    mma_bf16(acc[mi][ni], a[mi],
                             b[ni >> 1][(ni & 1) * 2],
                             b[ni >> 1][(ni & 1) * 2 + 1]);
        }
        __syncthreads();
    }

    const int g = lane >> 2, q = (lane & 3) << 1;
#pragma unroll
    for (int mi = 0; mi < 4; mi++) {
#pragma unroll
        for (int ni = 0; ni < 4; ni++) {
            int row = m0 + m_w + mi * 16 + g;
            int col = n0 + n_w + ni * 8 + q;
            *(float2*)(C + (size_t)row * N + col) =
                make_float2(acc[mi][ni][0], acc[mi][ni][1]);
            *(float2*)(C + (size_t)(row + 8) * N + col) =
                make_float2(acc[mi][ni][2], acc[mi][ni][3]);
        }
    }
}

// =================================================================
// Q post-process: RMSNorm + RoPE + scale, layout (B,H,T,HD)
// =================================================================
__global__ __launch_bounds__(128)
void qpost(const float* __restrict__ qraw, const float* __restrict__ cosb,
           const float* __restrict__ sinb, const float* __restrict__ qw,
           float* __restrict__ qrot)
{
    const int blk = blockIdx.x;
    const int h  = blk & (NH - 1);
    const int bt = blk >> 5;
    const int t  = bt & (SEQ_T - 1);
    const int b  = bt >> 10;
    const int d  = threadIdx.x;

    float v = qraw[(size_t)bt * QCOLS + h * HD + d];

    __shared__ float red[4];
    __shared__ float xs[HD];
    float ss = v * v;
#pragma unroll
    for (int o = 16; o > 0; o >>= 1) ss += __shfl_xor_sync(0xffffffffu, ss, o);
    if ((d & 31) == 0) red[d >> 5] = ss;
    __syncthreads();
    float tot = red[0] + red[1] + red[2] + red[3];
    float inv = rsqrtf(tot * (1.f / HD) + 1e-6f);
    float xn  = v * inv * qw[d];
    xs[d] = xn;
    __syncthreads();
    float other = xs[d ^ 64];
    float rot   = (d < 64) ? -other : other;
    int pos = L_PREV + t;
    float c = cosb[pos * HD + d];
    float s = sinb[pos * HD + d];
    float o = (xn * c + rot * s) * SCALE;
    qrot[(((size_t)b * NH + h) * SEQ_T + t) * HD + d] = o;
}

// =================================================================
// K/V post-process
// =================================================================
__global__ __launch_bounds__(128)
void kvpost(const float* __restrict__ kraw, const float* __restrict__ vraw,
            const float* __restrict__ cosb, const float* __restrict__ sinb,
            const float* __restrict__ kw,
            float* __restrict__ fullk, float* __restrict__ fullv)
{
    const int blk = blockIdx.x;
    const int h  = blk & (NKV - 1);
    const int bt = blk >> 3;
    const int t  = bt & (SEQ_T - 1);
    const int b  = bt >> 10;
    const int d  = threadIdx.x;

    float kv = kraw[(size_t)bt * KVCOLS + h * HD + d];
    float vv = vraw[(size_t)bt * KVCOLS + h * HD + d];

    __shared__ float red[4];
    __shared__ float xs[HD];
    float ss = kv * kv;
#pragma unroll
    for (int o = 16; o > 0; o >>= 1) ss += __shfl_xor_sync(0xffffffffu, ss, o);
    if ((d & 31) == 0) red[d >> 5] = ss;
    __syncthreads();
    float tot = red[0] + red[1] + red[2] + red[3];
    float inv = rsqrtf(tot * (1.f / HD) + 1e-6f);
    float xn  = kv * inv * kw[d];
    xs[d] = xn;
    __syncthreads();
    float other = xs[d ^ 64];
    float rot   = (d < 64) ? -other : other;
    int pos = L_PREV + t;
    float c = cosb[pos * HD + d];
    float s = sinb[pos * HD + d];
    float ko = xn * c + rot * s;

    size_t dst = (((size_t)b * NKV + h) * L_FULL + (L_PREV + t)) * HD + d;
    fullk[dst] = ko;
    fullv[dst] = vv;
}

// =================================================================
// Copy prev_k / prev_v into [0, L_PREV) of full_k/full_v
// =================================================================
__global__ __launch_bounds__(256)
void prev_copy(const float4* __restrict__ pk, const float4* __restrict__ pv,
               float4* __restrict__ outk, float4* __restrict__ outv)
{
    int i = blockIdx.x * blockDim.x + threadIdx.x;
    int chunk = i >> 15;
    int r = i & 32767;
    outk[(size_t)chunk * 65536 + r] = pk[i];
    outv[(size_t)chunk * 65536 + r] = pv[i];
}

// =================================================================
// Tensor-core flash attention (fp16 hi/lo, 3-term QK and PV).
// grid (T/64, NH, B), 128 threads = 4 warps; warp w owns q rows [16w,16w+16).
// SMEM: Kh, Kl, Vh, Vl each [64][136] fp16.
// =================================================================
#define FPAD 136
#define KH_OFF 0
#define KL_OFF (64 * FPAD * 2)            // 17408
#define VH_OFF (2 * 64 * FPAD * 2)        // 34816
#define VL_OFF (3 * 64 * FPAD * 2)        // 52224
#define ATTN_SMEM_BYTES (4 * 64 * FPAD * 2)   // 69632

__device__ __forceinline__ uint32_t pack_h(float a, float b) {
    __half2 h = __floats2half2_rn(a, b);
    return *(uint32_t*)&h;
}
__device__ __forceinline__ uint32_t pack_res(float a, float b, uint32_t hp) {
    __half2 h = *(__half2*)&hp;
    float2 f = __half22float2(h);
    __half2 l = __floats2half2_rn(a - f.x, b - f.y);
    return *(uint32_t*)&l;
}

__global__ __launch_bounds__(128)
void attn_tc(const float* __restrict__ q, const float* __restrict__ kfull,
             const float* __restrict__ vfull, float* __restrict__ ctx)
{
    extern __shared__ __align__(16) char sma[];
    const uint32_t sb = smem_u32(sma);

    const int bx = blockIdx.x;
    const int h  = blockIdx.y;
    const int b  = blockIdx.z;
    const int t0 = bx * 64;
    const int hkv = h >> 2;

    const int tid = threadIdx.x;
    const int lane = tid & 31, wid = tid >> 5;
    const int g = lane >> 2, qd = (lane & 3) << 1;   // qd = 2q

    // ---- load Q fragments (fp16 hi/lo) directly from gmem ----
    const float* qb = q + ((size_t)(b * NH + h) * SEQ_T + t0 + 16 * wid) * HD;
    uint32_t qh[8][4], ql[8][4];
#pragma unroll
    for (int c = 0; c < 8; c++) {
        float2 v0 = *(const float2*)(qb + (size_t)g * HD + 16 * c + qd);
        float2 v1 = *(const float2*)(qb + (size_t)(g + 8) * HD + 16 * c + qd);
        float2 v2 = *(const float2*)(qb + (size_t)g * HD + 16 * c + 8 + qd);
        float2 v3 = *(const float2*)(qb + (size_t)(g + 8) * HD + 16 * c + 8 + qd);
        qh[c][0] = pack_h(v0.x, v0.y); ql[c][0] = pack_res(v0.x, v0.y, qh[c][0]);
        qh[c][1] = pack_h(v1.x, v1.y); ql[c][1] = pack_res(v1.x, v1.y, qh[c][1]);
        qh[c][2] = pack_h(v2.x, v2.y); ql[c][2] = pack_res(v2.x, v2.y, qh[c][2]);
        qh[c][3] = pack_h(v3.x, v3.y); ql[c][3] = pack_res(v3.x, v3.y, qh[c][3]);
    }

    float acc[16][4];
#pragma unroll
    for (int nb = 0; nb < 16; nb++)
#pragma unroll
        for (int r = 0; r < 4; r++) acc[nb][r] = 0.f;
    float mA = -1e30f, mB = -1e30f, lA = 0.f, lB = 0.f;

    const float* kb = kfull + (size_t)(b * NKV + hkv) * L_FULL * HD;
    const float* vb = vfull + (size_t)(b * NKV + hkv) * L_FULL * HD;

    // lane-dependent ldmatrix base offsets (bytes)
    const uint32_t krow = (lane & 7) + ((lane >> 4) & 1) * 8;   // within 16-row pair
    const uint32_t kcol16 = ((lane >> 3) & 1) * 16;             // byte offset for k half
    const uint32_t kbase = krow * FPAD * 2 + kcol16;
    // V (trans): row = 16ck + ((lane>>3)&1)*8 + (lane&7); col byte = 16nb + ((lane>>4)&1)*16
    const uint32_t vrow = ((lane >> 3) & 1) * 8 + (lane & 7);
    const uint32_t vcol = ((lane >> 4) & 1) * 16;
    const uint32_t vbase = vrow * FPAD * 2 + vcol;

    const int ntiles = 17 + bx;

    for (int tile = 0; tile < ntiles; tile++) {
        __syncthreads();
        const int j0 = tile * 64;
        // load K/V tile, convert fp32 -> fp16 hi/lo
        for (int f = tid; f < 64 * 32; f += 128) {
            int r = f >> 5, c4 = (f & 31) * 4;
            float4 kv = *(const float4*)(kb + (size_t)(j0 + r) * HD + c4);
            float4 vv = *(const float4*)(vb + (size_t)(j0 + r) * HD + c4);
            uint32_t off = (r * FPAD + c4) * 2;
            __half2 h01 = __floats2half2_rn(kv.x, kv.y);
            __half2 h23 = __floats2half2_rn(kv.z, kv.w);
            float2 f01 = __half22float2(h01), f23 = __half22float2(h23);
            __half2 l01 = __floats2half2_rn(kv.x - f01.x, kv.y - f01.y);
            __half2 l23 = __floats2half2_rn(kv.z - f23.x, kv.w - f23.y);
            *(uint2*)(sma + KH_OFF + off) = make_uint2(*(uint32_t*)&h01, *(uint32_t*)&h23);
            *(uint2*)(sma + KL_OFF + off) = make_uint2(*(uint32_t*)&l01, *(uint32_t*)&l23);
            h01 = __floats2half2_rn(vv.x, vv.y);
            h23 = __floats2half2_rn(vv.z, vv.w);
            f01 = __half22float2(h01); f23 = __half22float2(h23);
            l01 = __floats2half2_rn(vv.x - f01.x, vv.y - f01.y);
            l23 = __floats2half2_rn(vv.z - f23.x, vv.w - f23.y);
            *(uint2*)(sma + VH_OFF + off) = make_uint2(*(uint32_t*)&h01, *(uint32_t*)&h23);
            *(uint2*)(sma + VL_OFF + off) = make_uint2(*(uint32_t*)&l01, *(uint32_t*)&l23);
        }
        __syncthreads();

        // ---- S = Q K^T (3 fp16 terms), S tile 16x64 per warp ----
        float s[8][4];
#pragma unroll
        for (int jb = 0; jb < 8; jb++)
#pragma unroll
            for (int r = 0; r < 4; r++) s[jb][r] = 0.f;

#pragma unroll
        for (int c = 0; c < 8; c++) {
#pragma unroll
            for (int p = 0; p < 4; p++) {
                uint32_t kh[4], kl[4];
                uint32_t off = (uint32_t)(p * 16 * FPAD * 2) + c * 32 + kbase;
                ldm_x4(sb + KH_OFF + off, kh);
                ldm_x4(sb + KL_OFF + off, kl);
                mma_f16(s[2 * p],     qh[c], kh[0], kh[1]);
                mma_f16(s[2 * p],     ql[c], kh[0], kh[1]);
                mma_f16(s[2 * p],     qh[c], kl[0], kl[1]);
                mma_f16(s[2 * p + 1], qh[c], kh[2], kh[3]);
                mma_f16(s[2 * p + 1], ql[c], kh[2], kh[3]);
                mma_f16(s[2 * p + 1], qh[c], kl[2], kl[3]);
            }
        }

        // ---- causal mask on last tile ----
        if (tile == ntiles - 1) {
            const int rowA = 16 * wid + g, rowB = rowA + 8;
#pragma unroll
            for (int jb = 0; jb < 8; jb++) {
                int col = 8 * jb + qd;
                if (col     > rowA) s[jb][0] = -1e30f;
                if (col + 1 > rowA) s[jb][1] = -1e30f;
                if (col     > rowB) s[jb][2] = -1e30f;
                if (col + 1 > rowB) s[jb][3] = -1e30f;
            }
        }

        // ---- online softmax (rows g and g+8) ----
        float mxA = s[0][0], mxB = s[0][2];
#pragma unroll
        for (int jb = 0; jb < 8; jb++) {
            mxA = fmaxf(mxA, fmaxf(s[jb][0], s[jb][1]));
            mxB = fmaxf(mxB, fmaxf(s[jb][2], s[jb][3]));
        }
        mxA = fmaxf(mxA, __shfl_xor_sync(0xffffffffu, mxA, 1));
        mxA = fmaxf(mxA, __shfl_xor_sync(0xffffffffu, mxA, 2));
        mxB = fmaxf(mxB, __shfl_xor_sync(0xffffffffu, mxB, 1));
        mxB = fmaxf(mxB, __shfl_xor_sync(0xffffffffu, mxB, 2));
        float nmA = fmaxf(mA, mxA), nmB = fmaxf(mB, mxB);
        float corrA = __expf(mA - nmA), corrB = __expf(mB - nmB);
        mA = nmA; mB = nmB;
        float rsA = 0.f, rsB = 0.f;
#pragma unroll
        for (int jb = 0; jb < 8; jb++) {
            s[jb][0] = __expf(s[jb][0] - nmA); rsA += s[jb][0];
            s[jb][1] = __expf(s[jb][1] - nmA); rsA += s[jb][1];
            s[jb][2] = __expf(s[jb][2] - nmB); rsB += s[jb][2];
            s[jb][3] = __expf(s[jb][3] - nmB); rsB += s[jb][3];
        }
        rsA += __shfl_xor_sync(0xffffffffu, rsA, 1);
        rsA += __shfl_xor_sync(0xffffffffu, rsA, 2);
        rsB += __shfl_xor_sync(0xffffffffu, rsB, 1);
        rsB += __shfl_xor_sync(0xffffffffu, rsB, 2);
        lA = lA * corrA + rsA;
        lB = lB * corrB + rsB;
#pragma unroll
        for (int nb = 0; nb < 16; nb++) {
            acc[nb][0] *= corrA; acc[nb][1] *= corrA;
            acc[nb][2] *= corrB; acc[nb][3] *= corrB;
        }

        // ---- PV (3 fp16 terms) ----
#pragma unroll
        for (int ck = 0; ck < 4; ck++) {
            uint32_t ph[4], pl[4];
            ph[0] = pack_h(s[2 * ck][0], s[2 * ck][1]);
            pl[0] = pack_res(s[2 * ck][0], s[2 * ck][1], ph[0]);
            ph[1] = pack_h(s[2 * ck][2], s[2 * ck][3]);
            pl[1] = pack_res(s[2 * ck][2], s[2 * ck][3], ph[1]);
            ph[2] = pack_h(s[2 * ck + 1][0], s[2 * ck + 1][1]);
            pl[2] = pack_res(s[2 * ck + 1][0], s[2 * ck + 1][1], ph[2]);
            ph[3] = pack_h(s[2 * ck + 1][2], s[2 * ck + 1][3]);
            pl[3] = pack_res(s[2 * ck + 1][2], s[2 * ck + 1][3], ph[3]);
#pragma unroll
            for (int np = 0; np < 8; np++) {
                uint32_t vh[4], vl[4];
                uint32_t off = (uint32_t)(ck * 16 * FPAD * 2) + np * 32 + vbase;
                ldm_x4_t(sb + VH_OFF + off, vh);
                ldm_x4_t(sb + VL_OFF + off, vl);
                mma_f16(acc[2 * np],     ph, vh[0], vh[1]);
                mma_f16(acc[2 * np],     pl, vh[0], vh[1]);
                mma_f16(acc[2 * np],     ph, vl[0], vl[1]);
                mma_f16(acc[2 * np + 1], ph, vh[2], vh[3]);
                mma_f16(acc[2 * np + 1], pl, vh[2], vh[3]);
                mma_f16(acc[2 * np + 1], ph, vl[2], vl[3]);
            }
        }
    }

    // ---- epilogue ----
    const float invA = 1.f / lA, invB = 1.f / lB;
    const int trow = t0 + 16 * wid + g;
    float* oA = ctx + ((size_t)b * SEQ_T + trow) * QCOLS + h * HD;
    float* oB = ctx + ((size_t)b * SEQ_T + trow + 8) * QCOLS + h * HD;
#pragma unroll
    for (int nb = 0; nb < 16; nb++) {
        int col = nb * 8 + qd;
        *(float2*)(oA + col) = make_float2(acc[nb][0] * invA, acc[nb][1] * invA);
        *(float2*)(oB + col) = make_float2(acc[nb][2] * invB, acc[nb][3] * invB);
    }
}

// =================================================================
// Launch
// =================================================================
extern "C" void kernel_launch(void* const* d_in, const int* in_sizes, int n_in,
                              void* d_out, int out_size)
{
    const float* x      = (const float*)d_in[0];
    const float* cosb   = (const float*)d_in[2];
    const float* sinb   = (const float*)d_in[3];
    const float* prev_k = (const float*)d_in[5];
    const float* prev_v = (const float*)d_in[6];
    const float* Wq     = (const float*)d_in[7];
    const float* Wk     = (const float*)d_in[8];
    const float* Wv     = (const float*)d_in[9];
    const float* Wo     = (const float*)d_in[10];
    const float* qw     = (const float*)d_in[11];
    const float* kw     = (const float*)d_in[12];

    float* out   = (float*)d_out;
    float* fullk = out + (size_t)MROWS * D_IN;
    float* fullv = fullk + (size_t)BATCH * NKV * L_FULL * HD;

    float *qraw, *kraw, *vraw, *qrot, *ctx;
    __nv_bfloat16 *x3, *w3q, *w3k, *w3v, *w3o, *ctx3;
    cudaGetSymbolAddress((void**)&qraw, g_qraw);
    cudaGetSymbolAddress((void**)&kraw, g_kraw);
    cudaGetSymbolAddress((void**)&vraw, g_vraw);
    cudaGetSymbolAddress((void**)&qrot, g_qrot);
    cudaGetSymbolAddress((void**)&ctx,  g_ctx);
    cudaGetSymbolAddress((void**)&x3,   g_x3);
    cudaGetSymbolAddress((void**)&w3q,  g_w3q);
    cudaGetSymbolAddress((void**)&w3k,  g_w3k);
    cudaGetSymbolAddress((void**)&w3v,  g_w3v);
    cudaGetSymbolAddress((void**)&w3o,  g_w3o);
    cudaGetSymbolAddress((void**)&ctx3, g_ctx3);

    cudaFuncSetAttribute(gemm_bf16, cudaFuncAttributeMaxDynamicSharedMemorySize,
                         GEMM_SMEM_BYTES);
    cudaFuncSetAttribute(attn_tc, cudaFuncAttributeMaxDynamicSharedMemorySize,
                         ATTN_SMEM_BYTES);

    // 0) split operands to bf16 [hi|lo|hi] / [hi|hi|lo]
    {
        int n4;
        n4 = MROWS * D_IN / 4;
        split3<<<n4 / 256, 256>>>((const float4*)x, x3, D_IN, 9, n4, 0);
        n4 = QCOLS * D_IN / 4;
        split3<<<n4 / 256, 256>>>((const float4*)Wq, w3q, D_IN, 9, n4, 1);
        n4 = KVCOLS * D_IN / 4;
        split3<<<n4 / 256, 256>>>((const float4*)Wk, w3k, D_IN, 9, n4, 1);
        split3<<<n4 / 256, 256>>>((const float4*)Wv, w3v, D_IN, 9, n4, 1);
        n4 = D_IN * QCOLS / 4;
        split3<<<n4 / 256, 256>>>((const float4*)Wo, w3o, QCOLS, 10, n4, 1);
    }

    // 1) projections
    gemm_bf16<<<dim3(QCOLS / 128, MROWS / 128), 256, GEMM_SMEM_BYTES>>>(
        x3, w3q, qraw, QCOLS, 3 * D_IN);
    gemm_bf16<<<dim3(KVCOLS / 128, MROWS / 128), 256, GEMM_SMEM_BYTES>>>(
        x3, w3k, kraw, KVCOLS, 3 * D_IN);
    gemm_bf16<<<dim3(KVCOLS / 128, MROWS / 128), 256, GEMM_SMEM_BYTES>>>(
        x3, w3v, vraw, KVCOLS, 3 * D_IN);

    // 2) norm + rope + cache assembly
    qpost<<<MROWS * NH, 128>>>(qraw, cosb, sinb, qw, qrot);
    kvpost<<<MROWS * NKV, 128>>>(kraw, vraw, cosb, sinb, kw, fullk, fullv);
    prev_copy<<<2048, 256>>>((const float4*)prev_k, (const float4*)prev_v,
                             (float4*)fullk, (float4*)fullv);

    // 3) attention -> ctx (tensor core)
    attn_tc<<<dim3(SEQ_T / 64, NH, BATCH), 128, ATTN_SMEM_BYTES>>>(
        qrot, fullk, fullv, ctx);

    // 4) output projection
    {
        int n4 = MROWS * QCOLS / 4;
        split3<<<n4 / 256, 256>>>((const float4*)ctx, ctx3, QCOLS, 10, n4, 0);
    }
    gemm_bf16<<<dim3(D_IN / 128, MROWS / 128), 256, GEMM_SMEM_BYTES>>>(
        ctx3, w3o, out, D_IN, 3 * QCOLS);
}

// round 6
// speedup vs baseline: 3.0508x; 1.0808x over previous
#include <cuda_runtime.h>
#include <cuda_bf16.h>
#include <cuda_fp16.h>
#include <cstdint>
#include <math.h>

// ---------------- Problem constants ----------------
#define BATCH   2
#define SEQ_T   1024
#define D_IN    2048
#define NH      32
#define NKV     8
#define HD      128
#define L_PREV  1024
#define L_FULL  2048
#define SCALE   0.08838834764831845f // 1/sqrt(128)

#define MROWS   (BATCH * SEQ_T)     // 2048
#define QCOLS   (NH * HD)           // 4096
#define KVCOLS  (NKV * HD)          // 1024
#define KVTOT   (BATCH * NKV * L_FULL * HD)   // 4M elements

// ---------------- Scratch (static device globals; no allocation) ----------------
__device__ float g_qraw[MROWS * QCOLS];
__device__ float g_kraw[MROWS * KVCOLS];
__device__ float g_vraw[MROWS * KVCOLS];
__device__ float g_qrot[MROWS * QCOLS];          // (B,H,T,HD)
__device__ float g_ctx [MROWS * QCOLS];          // (B,T,H*HD)

// bf16 split-3 operand buffers for GEMMs
__device__ __nv_bfloat16 g_x3  [MROWS * 3 * D_IN];
__device__ __nv_bfloat16 g_w3q [QCOLS * 3 * D_IN];
__device__ __nv_bfloat16 g_w3k [KVCOLS * 3 * D_IN];
__device__ __nv_bfloat16 g_w3v [KVCOLS * 3 * D_IN];
__device__ __nv_bfloat16 g_w3o [D_IN * 3 * QCOLS];
__device__ __nv_bfloat16 g_ctx3[MROWS * 3 * QCOLS];

// fp16 hi/lo K/V for attention
__device__ __half g_kh[KVTOT];
__device__ __half g_kl[KVTOT];
__device__ __half g_vh[KVTOT];
__device__ __half g_vl[KVTOT];

__device__ __forceinline__ uint32_t smem_u32(const void* p) {
    uint32_t a;
    asm("{ .reg .u64 t; cvta.to.shared.u64 t, %1; cvt.u32.u64 %0, t; }"
        : "=r"(a) : "l"(p));
    return a;
}

// fp32x4 -> (hi 4xbf16, lo 4xbf16)
__device__ __forceinline__ void hilo4(float4 v, uint2& hp, uint2& lp) {
    __nv_bfloat162 h01 = __floats2bfloat162_rn(v.x, v.y);
    __nv_bfloat162 h23 = __floats2bfloat162_rn(v.z, v.w);
    float2 f01 = __bfloat1622float2(h01);
    float2 f23 = __bfloat1622float2(h23);
    __nv_bfloat162 l01 = __floats2bfloat162_rn(v.x - f01.x, v.y - f01.y);
    __nv_bfloat162 l23 = __floats2bfloat162_rn(v.z - f23.x, v.w - f23.y);
    hp = make_uint2(*(uint32_t*)&h01, *(uint32_t*)&h23);
    lp = make_uint2(*(uint32_t*)&l01, *(uint32_t*)&l23);
}
// fp32x4 -> (hi 4xfp16, lo 4xfp16)
__device__ __forceinline__ void hilo4h(float4 v, uint2& hp, uint2& lp) {
    __half2 h01 = __floats2half2_rn(v.x, v.y);
    __half2 h23 = __floats2half2_rn(v.z, v.w);
    float2 f01 = __half22float2(h01);
    float2 f23 = __half22float2(h23);
    __half2 l01 = __floats2half2_rn(v.x - f01.x, v.y - f01.y);
    __half2 l23 = __floats2half2_rn(v.z - f23.x, v.w - f23.y);
    hp = make_uint2(*(uint32_t*)&h01, *(uint32_t*)&h23);
    lp = make_uint2(*(uint32_t*)&l01, *(uint32_t*)&l23);
}

// =================================================================
// split3: src[R][K] fp32 -> dst[R][3K] bf16.
// modeB=0: [hi|lo|hi]  (A);  modeB=1: [hi|hi|lo]  (B)
// =================================================================
__global__ __launch_bounds__(256)
void split3(const float4* __restrict__ src, __nv_bfloat16* __restrict__ dst,
            int K, int s4, int n4, int modeB)
{
    for (int idx = blockIdx.x * blockDim.x + threadIdx.x; idx < n4;
         idx += gridDim.x * blockDim.x) {
        int row = idx >> s4;
        int c4  = (idx - (row << s4)) << 2;
        float4 v = src[idx];
        uint2 hp, lp;
        hilo4(v, hp, lp);
        size_t base = (size_t)row * 3 * K + c4;
        *(uint2*)(dst + base)         = hp;
        *(uint2*)(dst + base + K)     = modeB ? hp : lp;
        *(uint2*)(dst + base + 2 * K) = modeB ? lp : hp;
    }
}

// =================================================================
// mma.sync helpers
// =================================================================
__device__ __forceinline__ void ldm_x4(uint32_t addr, uint32_t r[4]) {
    asm volatile("ldmatrix.sync.aligned.m8n8.x4.shared.b16 {%0,%1,%2,%3}, [%4];"
                 : "=r"(r[0]), "=r"(r[1]), "=r"(r[2]), "=r"(r[3]) : "r"(addr));
}
__device__ __forceinline__ void ldm_x4_t(uint32_t addr, uint32_t r[4]) {
    asm volatile("ldmatrix.sync.aligned.m8n8.x4.trans.shared.b16 {%0,%1,%2,%3}, [%4];"
                 : "=r"(r[0]), "=r"(r[1]), "=r"(r[2]), "=r"(r[3]) : "r"(addr));
}
__device__ __forceinline__ void mma_bf16(float d[4], const uint32_t a[4],
                                         uint32_t b0, uint32_t b1) {
    asm volatile(
        "mma.sync.aligned.m16n8k16.row.col.f32.bf16.bf16.f32 "
        "{%0,%1,%2,%3}, {%4,%5,%6,%7}, {%8,%9}, {%0,%1,%2,%3};"
        : "+f"(d[0]), "+f"(d[1]), "+f"(d[2]), "+f"(d[3])
        : "r"(a[0]), "r"(a[1]), "r"(a[2]), "r"(a[3]), "r"(b0), "r"(b1));
}
__device__ __forceinline__ void mma_f16(float d[4], const uint32_t a[4],
                                        uint32_t b0, uint32_t b1) {
    asm volatile(
        "mma.sync.aligned.m16n8k16.row.col.f32.f16.f16.f32 "
        "{%0,%1,%2,%3}, {%4,%5,%6,%7}, {%8,%9}, {%0,%1,%2,%3};"
        : "+f"(d[0]), "+f"(d[1]), "+f"(d[2]), "+f"(d[3])
        : "r"(a[0]), "r"(a[1]), "r"(a[2]), "r"(a[3]), "r"(b0), "r"(b1));
}
__device__ __forceinline__ void cp16(uint32_t dst, const void* src) {
    asm volatile("cp.async.cg.shared.global [%0], [%1], 16;" :: "r"(dst), "l"(src));
}
__device__ __forceinline__ void cp_commit() { asm volatile("cp.async.commit_group;"); }
__device__ __forceinline__ void cp_wait0()  { asm volatile("cp.async.wait_group 0;"); }
__device__ __forceinline__ void cp_wait1()  { asm volatile("cp.async.wait_group 1;"); }

// =================================================================
// bf16 GEMM  C[M,N] = A3[M,K3] * B3[N,K3]^T  (pre-split bf16)
// 128x128 tile, BK=64, 3-stage cp.async pipeline, 256 threads.
// =================================================================
#define APITCH 72
#define GSTG   (128 * APITCH * 2)         // 18432 B per stage per matrix
#define GEMM_SMEM_BYTES (6 * GSTG)        // 110592

__global__ __launch_bounds__(256, 2)
void gemm_bf16(const __nv_bfloat16* __restrict__ A,
               const __nv_bfloat16* __restrict__ Bm,
               float* __restrict__ C, int N, int K3)
{
    extern __shared__ __align__(16) char smg[];
    const uint32_t sb = smem_u32(smg);

    const int tid = threadIdx.x;
    const int lane = tid & 31, wid = tid >> 5;
    const int m0 = blockIdx.y * 128, n0 = blockIdx.x * 128;
    const int m_w = (wid & 1) * 64, n_w = (wid >> 1) * 32;

    const int tA = lane >> 3;
    const int a_m = (lane & 7) + ((tA & 1) << 3);
    const int a_k = (tA >> 1) << 3;
    const int b_n = (lane & 7) + ((tA >> 1) << 3);
    const int b_k = (tA & 1) << 3;

    float acc[4][4][4];
#pragma unroll
    for (int mi = 0; mi < 4; mi++)
#pragma unroll
        for (int ni = 0; ni < 4; ni++)
#pragma unroll
            for (int r = 0; r < 4; r++) acc[mi][ni][r] = 0.f;

    const int nkt = K3 >> 6;

    auto load_stage = [&](int kt, int s) {
        const __nv_bfloat16* Ap = A + (size_t)m0 * K3 + kt * 64;
        const __nv_bfloat16* Bp = Bm + (size_t)n0 * K3 + kt * 64;
#pragma unroll
        for (int i = 0; i < 4; i++) {
            int f = tid + (i << 8);
            int row = f >> 3;
            int c = (f & 7) << 3;
            cp16(sb + s * GSTG + (row * APITCH + c) * 2, Ap + (size_t)row * K3 + c);
            cp16(sb + 3 * GSTG + s * GSTG + (row * APITCH + c) * 2,
                 Bp + (size_t)row * K3 + c);
        }
    };

    load_stage(0, 0); cp_commit();
    if (nkt > 1) { load_stage(1, 1); cp_commit(); }

    for (int kt = 0; kt < nkt; kt++) {
        const int s = kt % 3;
        if (kt + 1 < nkt) cp_wait1(); else cp_wait0();
        __syncthreads();
        if (kt + 2 < nkt) { load_stage(kt + 2, (kt + 2) % 3); cp_commit(); }

        const uint32_t as = sb + s * GSTG;
        const uint32_t bs = sb + 3 * GSTG + s * GSTG;
#pragma unroll
        for (int ks = 0; ks < 4; ks++) {
            uint32_t a[4][4];
#pragma unroll
            for (int mi = 0; mi < 4; mi++)
                ldm_x4(as + ((m_w + mi * 16 + a_m) * APITCH + ks * 16 + a_k) * 2, a[mi]);
            uint32_t b[2][4];
#pragma unroll
            for (int pi = 0; pi < 2; pi++)
                ldm_x4(bs + ((n_w + pi * 16 + b_n) * APITCH + ks * 16 + b_k) * 2, b[pi]);
#pragma unroll
            for (int mi = 0; mi < 4; mi++)
#pragma unroll
                for (int ni = 0; ni < 4; ni++)
                    mma_bf16(acc[mi][ni], a[mi],
                             b[ni >> 1][(ni & 1) * 2],
                             b[ni >> 1][(ni & 1) * 2 + 1]);
        }
    }

    const int g = lane >> 2, q = (lane & 3) << 1;
#pragma unroll
    for (int mi = 0; mi < 4; mi++) {
#pragma unroll
        for (int ni = 0; ni < 4; ni++) {
            int row = m0 + m_w + mi * 16 + g;
            int col = n0 + n_w + ni * 8 + q;
            *(float2*)(C + (size_t)row * N + col) =
                make_float2(acc[mi][ni][0], acc[mi][ni][1]);
            *(float2*)(C + (size_t)(row + 8) * N + col) =
                make_float2(acc[mi][ni][2], acc[mi][ni][3]);
        }
    }
}

// =================================================================
// Q post-process: RMSNorm + RoPE + scale, layout (B,H,T,HD)
// =================================================================
__global__ __launch_bounds__(128)
void qpost(const float* __restrict__ qraw, const float* __restrict__ cosb,
           const float* __restrict__ sinb, const float* __restrict__ qw,
           float* __restrict__ qrot)
{
    const int blk = blockIdx.x;
    const int h  = blk & (NH - 1);
    const int bt = blk >> 5;
    const int t  = bt & (SEQ_T - 1);
    const int b  = bt >> 10;
    const int d  = threadIdx.x;

    float v = qraw[(size_t)bt * QCOLS + h * HD + d];

    __shared__ float red[4];
    __shared__ float xs[HD];
    float ss = v * v;
#pragma unroll
    for (int o = 16; o > 0; o >>= 1) ss += __shfl_xor_sync(0xffffffffu, ss, o);
    if ((d & 31) == 0) red[d >> 5] = ss;
    __syncthreads();
    float tot = red[0] + red[1] + red[2] + red[3];
    float inv = rsqrtf(tot * (1.f / HD) + 1e-6f);
    float xn  = v * inv * qw[d];
    xs[d] = xn;
    __syncthreads();
    float other = xs[d ^ 64];
    float rot   = (d < 64) ? -other : other;
    int pos = L_PREV + t;
    float c = cosb[pos * HD + d];
    float s = sinb[pos * HD + d];
    float o = (xn * c + rot * s) * SCALE;
    qrot[(((size_t)b * NH + h) * SEQ_T + t) * HD + d] = o;
}

// =================================================================
// K/V post-process: writes fp32 cache + fp16 hi/lo split caches
// =================================================================
__global__ __launch_bounds__(128)
void kvpost(const float* __restrict__ kraw, const float* __restrict__ vraw,
            const float* __restrict__ cosb, const float* __restrict__ sinb,
            const float* __restrict__ kw,
            float* __restrict__ fullk, float* __restrict__ fullv,
            __half* __restrict__ kh, __half* __restrict__ kl,
            __half* __restrict__ vh, __half* __restrict__ vl)
{
    const int blk = blockIdx.x;
    const int h  = blk & (NKV - 1);
    const int bt = blk >> 3;
    const int t  = bt & (SEQ_T - 1);
    const int b  = bt >> 10;
    const int d  = threadIdx.x;

    float kv = kraw[(size_t)bt * KVCOLS + h * HD + d];
    float vv = vraw[(size_t)bt * KVCOLS + h * HD + d];

    __shared__ float red[4];
    __shared__ float xs[HD];
    float ss = kv * kv;
#pragma unroll
    for (int o = 16; o > 0; o >>= 1) ss += __shfl_xor_sync(0xffffffffu, ss, o);
    if ((d & 31) == 0) red[d >> 5] = ss;
    __syncthreads();
    float tot = red[0] + red[1] + red[2] + red[3];
    float inv = rsqrtf(tot * (1.f / HD) + 1e-6f);
    float xn  = kv * inv * kw[d];
    xs[d] = xn;
    __syncthreads();
    float other = xs[d ^ 64];
    float rot   = (d < 64) ? -other : other;
    int pos = L_PREV + t;
    float c = cosb[pos * HD + d];
    float s = sinb[pos * HD + d];
    float ko = xn * c + rot * s;

    size_t dst = (((size_t)b * NKV + h) * L_FULL + (L_PREV + t)) * HD + d;
    fullk[dst] = ko;
    fullv[dst] = vv;

    __half kh16 = __float2half_rn(ko);
    __half vh16 = __float2half_rn(vv);
    kh[dst] = kh16; kl[dst] = __float2half_rn(ko - __half2float(kh16));
    vh[dst] = vh16; vl[dst] = __float2half_rn(vv - __half2float(vh16));
}

// =================================================================
// Copy prev_k/prev_v into [0, L_PREV) + fp16 hi/lo split
// =================================================================
__global__ __launch_bounds__(256)
void prev_copy(const float4* __restrict__ pk, const float4* __restrict__ pv,
               float4* __restrict__ outk, float4* __restrict__ outv,
               uint2* __restrict__ kh4, uint2* __restrict__ kl4,
               uint2* __restrict__ vh4, uint2* __restrict__ vl4)
{
    int i = blockIdx.x * blockDim.x + threadIdx.x;   // 0 .. 524287
    int chunk = i >> 15;                             // (b*NKV + h)
    int r = i & 32767;
    size_t dst = (size_t)chunk * 65536 + r;
    float4 k = pk[i], v = pv[i];
    outk[dst] = k;
    outv[dst] = v;
    uint2 hp, lp;
    hilo4h(k, hp, lp);
    kh4[dst] = hp; kl4[dst] = lp;
    hilo4h(v, hp, lp);
    vh4[dst] = hp; vl4[dst] = lp;
}

// =================================================================
// Tensor-core flash attention (fp16 hi/lo, 3-term QK and PV).
// grid (T/128, NH, B), 256 threads = 8 warps; warp w owns q rows [16w,16w+16).
// K/V fp16 hi/lo preloaded from gmem via cp.async, double-buffered.
// =================================================================
#define FPAD 136
#define KH_OFF 0
#define KL_OFF 17408
#define VH_OFF 34816
#define VL_OFF 52224
#define AST    69632                         // stage stride
#define ATTN_SMEM_BYTES (2 * AST)            // 139264

__device__ __forceinline__ uint32_t pack_h(float a, float b) {
    __half2 h = __floats2half2_rn(a, b);
    return *(uint32_t*)&h;
}
__device__ __forceinline__ uint32_t pack_res(float a, float b, uint32_t hp) {
    __half2 h = *(__half2*)&hp;
    float2 f = __half22float2(h);
    __half2 l = __floats2half2_rn(a - f.x, b - f.y);
    return *(uint32_t*)&l;
}

__global__ __launch_bounds__(256, 1)
void attn_tc(const float* __restrict__ q,
             const __half* __restrict__ khg, const __half* __restrict__ klg,
             const __half* __restrict__ vhg, const __half* __restrict__ vlg,
             float* __restrict__ ctx)
{
    extern __shared__ __align__(16) char sma[];
    const uint32_t sb = smem_u32(sma);

    const int bx = blockIdx.x;
    const int h  = blockIdx.y;
    const int b  = blockIdx.z;
    const int t0 = bx * 128;
    const int hkv = h >> 2;

    const int tid = threadIdx.x;
    const int lane = tid & 31, wid = tid >> 5;
    const int g = lane >> 2, qd = (lane & 3) << 1;

    // ---- Q fragments (fp16 hi/lo) from gmem fp32 ----
    const float* qb = q + ((size_t)(b * NH + h) * SEQ_T + t0 + 16 * wid) * HD;
    uint32_t qh[8][4], ql[8][4];
#pragma unroll
    for (int c = 0; c < 8; c++) {
        float2 v0 = *(const float2*)(qb + (size_t)g * HD + 16 * c + qd);
        float2 v1 = *(const float2*)(qb + (size_t)(g + 8) * HD + 16 * c + qd);
        float2 v2 = *(const float2*)(qb + (size_t)g * HD + 16 * c + 8 + qd);
        float2 v3 = *(const float2*)(qb + (size_t)(g + 8) * HD + 16 * c + 8 + qd);
        qh[c][0] = pack_h(v0.x, v0.y); ql[c][0] = pack_res(v0.x, v0.y, qh[c][0]);
        qh[c][1] = pack_h(v1.x, v1.y); ql[c][1] = pack_res(v1.x, v1.y, qh[c][1]);
        qh[c][2] = pack_h(v2.x, v2.y); ql[c][2] = pack_res(v2.x, v2.y, qh[c][2]);
        qh[c][3] = pack_h(v3.x, v3.y); ql[c][3] = pack_res(v3.x, v3.y, qh[c][3]);
    }

    float acc[16][4];
#pragma unroll
    for (int nb = 0; nb < 16; nb++)
#pragma unroll
        for (int r = 0; r < 4; r++) acc[nb][r] = 0.f;
    float mA = -1e30f, mB = -1e30f, lA = 0.f, lB = 0.f;

    const size_t kvbase = (size_t)(b * NKV + hkv) * L_FULL * HD;
    const __half* khb = khg + kvbase;
    const __half* klb = klg + kvbase;
    const __half* vhb = vhg + kvbase;
    const __half* vlb = vlg + kvbase;

    const uint32_t krow = (lane & 7) + ((lane >> 4) & 1) * 8;
    const uint32_t kcol16 = ((lane >> 3) & 1) * 16;
    const uint32_t kbase = krow * FPAD * 2 + kcol16;
    const uint32_t vrow = ((lane >> 3) & 1) * 8 + (lane & 7);
    const uint32_t vcol = ((lane >> 4) & 1) * 16;
    const uint32_t vbase = vrow * FPAD * 2 + vcol;

    const int ntiles = 18 + 2 * bx;

    auto load_tile = [&](int tile, int st) {
        const int j0 = tile * 64;
        const uint32_t base = sb + st * AST;
        for (int f = tid; f < 1024; f += 256) {
            int r = f >> 4, c = (f & 15) << 3;
            uint32_t off = (uint32_t)(r * FPAD + c) * 2;
            size_t src = (size_t)(j0 + r) * HD + c;
            cp16(base + KH_OFF + off, khb + src);
            cp16(base + KL_OFF + off, klb + src);
            cp16(base + VH_OFF + off, vhb + src);
            cp16(base + VL_OFF + off, vlb + src);
        }
    };

    load_tile(0, 0); cp_commit();

    for (int tile = 0; tile < ntiles; tile++) {
        const int st = tile & 1;
        cp_wait0();
        __syncthreads();
        if (tile + 1 < ntiles) { load_tile(tile + 1, st ^ 1); cp_commit(); }
        const uint32_t sbase = sb + st * AST;

        // ---- S = Q K^T (3 fp16 terms), 16x64 per warp ----
        float s[8][4];
#pragma unroll
        for (int jb = 0; jb < 8; jb++)
#pragma unroll
            for (int r = 0; r < 4; r++) s[jb][r] = 0.f;

#pragma unroll
        for (int c = 0; c < 8; c++) {
#pragma unroll
            for (int p = 0; p < 4; p++) {
                uint32_t kh[4], kl[4];
                uint32_t off = (uint32_t)(p * 16 * FPAD * 2) + c * 32 + kbase;
                ldm_x4(sbase + KH_OFF + off, kh);
                ldm_x4(sbase + KL_OFF + off, kl);
                mma_f16(s[2 * p],     qh[c], kh[0], kh[1]);
                mma_f16(s[2 * p],     ql[c], kh[0], kh[1]);
                mma_f16(s[2 * p],     qh[c], kl[0], kl[1]);
                mma_f16(s[2 * p + 1], qh[c], kh[2], kh[3]);
                mma_f16(s[2 * p + 1], ql[c], kh[2], kh[3]);
                mma_f16(s[2 * p + 1], qh[c], kl[2], kl[3]);
            }
        }

        // ---- causal mask (last two tiles) ----
        if (tile >= ntiles - 2) {
            const int j0 = tile * 64;
            const int rowA = t0 + 16 * wid + g;     // q index in seq
            const int limA = L_PREV + rowA;          // max allowed key
            const int limB = limA + 8;
#pragma unroll
            for (int jb = 0; jb < 8; jb++) {
                int col = j0 + 8 * jb + qd;
                if (col     > limA) s[jb][0] = -1e30f;
                if (col + 1 > limA) s[jb][1] = -1e30f;
                if (col     > limB) s[jb][2] = -1e30f;
                if (col + 1 > limB) s[jb][3] = -1e30f;
            }
        }

        // ---- online softmax ----
        float mxA = s[0][0], mxB = s[0][2];
#pragma unroll
        for (int jb = 0; jb < 8; jb++) {
            mxA = fmaxf(mxA, fmaxf(s[jb][0], s[jb][1]));
            mxB = fmaxf(mxB, fmaxf(s[jb][2], s[jb][3]));
        }
        mxA = fmaxf(mxA, __shfl_xor_sync(0xffffffffu, mxA, 1));
        mxA = fmaxf(mxA, __shfl_xor_sync(0xffffffffu, mxA, 2));
        mxB = fmaxf(mxB, __shfl_xor_sync(0xffffffffu, mxB, 1));
        mxB = fmaxf(mxB, __shfl_xor_sync(0xffffffffu, mxB, 2));
        float nmA = fmaxf(mA, mxA), nmB = fmaxf(mB, mxB);
        float corrA = __expf(mA - nmA), corrB = __expf(mB - nmB);
        mA = nmA; mB = nmB;
        float rsA = 0.f, rsB = 0.f;
#pragma unroll
        for (int jb = 0; jb < 8; jb++) {
            s[jb][0] = __expf(s[jb][0] - nmA); rsA += s[jb][0];
            s[jb][1] = __expf(s[jb][1] - nmA); rsA += s[jb][1];
            s[jb][2] = __expf(s[jb][2] - nmB); rsB += s[jb][2];
            s[jb][3] = __expf(s[jb][3] - nmB); rsB += s[jb][3];
        }
        rsA += __shfl_xor_sync(0xffffffffu, rsA, 1);
        rsA += __shfl_xor_sync(0xffffffffu, rsA, 2);
        rsB += __shfl_xor_sync(0xffffffffu, rsB, 1);
        rsB += __shfl_xor_sync(0xffffffffu, rsB, 2);
        lA = lA * corrA + rsA;
        lB = lB * corrB + rsB;
#pragma unroll
        for (int nb = 0; nb < 16; nb++) {
            acc[nb][0] *= corrA; acc[nb][1] *= corrA;
            acc[nb][2] *= corrB; acc[nb][3] *= corrB;
        }

        // ---- PV (3 fp16 terms) ----
#pragma unroll
        for (int ck = 0; ck < 4; ck++) {
            uint32_t ph[4], pl[4];
            ph[0] = pack_h(s[2 * ck][0], s[2 * ck][1]);
            pl[0] = pack_res(s[2 * ck][0], s[2 * ck][1], ph[0]);
            ph[1] = pack_h(s[2 * ck][2], s[2 * ck][3]);
            pl[1] = pack_res(s[2 * ck][2], s[2 * ck][3], ph[1]);
            ph[2] = pack_h(s[2 * ck + 1][0], s[2 * ck + 1][1]);
            pl[2] = pack_res(s[2 * ck + 1][0], s[2 * ck + 1][1], ph[2]);
            ph[3] = pack_h(s[2 * ck + 1][2], s[2 * ck + 1][3]);
            pl[3] = pack_res(s[2 * ck + 1][2], s[2 * ck + 1][3], ph[3]);
#pragma unroll
            for (int np = 0; np < 8; np++) {
                uint32_t vh[4], vl[4];
                uint32_t off = (uint32_t)(ck * 16 * FPAD * 2) + np * 32 + vbase;
                ldm_x4_t(sbase + VH_OFF + off, vh);
                ldm_x4_t(sbase + VL_OFF + off, vl);
                mma_f16(acc[2 * np],     ph, vh[0], vh[1]);
                mma_f16(acc[2 * np],     pl, vh[0], vh[1]);
                mma_f16(acc[2 * np],     ph, vl[0], vl[1]);
                mma_f16(acc[2 * np + 1], ph, vh[2], vh[3]);
                mma_f16(acc[2 * np + 1], pl, vh[2], vh[3]);
                mma_f16(acc[2 * np + 1], ph, vl[2], vl[3]);
            }
        }
    }

    // ---- epilogue ----
    const float invA = 1.f / lA, invB = 1.f / lB;
    const int trow = t0 + 16 * wid + g;
    float* oA = ctx + ((size_t)b * SEQ_T + trow) * QCOLS + h * HD;
    float* oB = ctx + ((size_t)b * SEQ_T + trow + 8) * QCOLS + h * HD;
#pragma unroll
    for (int nb = 0; nb < 16; nb++) {
        int col = nb * 8 + qd;
        *(float2*)(oA + col) = make_float2(acc[nb][0] * invA, acc[nb][1] * invA);
        *(float2*)(oB + col) = make_float2(acc[nb][2] * invB, acc[nb][3] * invB);
    }
}

// =================================================================
// Launch
// =================================================================
extern "C" void kernel_launch(void* const* d_in, const int* in_sizes, int n_in,
                              void* d_out, int out_size)
{
    const float* x      = (const float*)d_in[0];
    const float* cosb   = (const float*)d_in[2];
    const float* sinb   = (const float*)d_in[3];
    const float* prev_k = (const float*)d_in[5];
    const float* prev_v = (const float*)d_in[6];
    const float* Wq     = (const float*)d_in[7];
    const float* Wk     = (const float*)d_in[8];
    const float* Wv     = (const float*)d_in[9];
    const float* Wo     = (const float*)d_in[10];
    const float* qw     = (const float*)d_in[11];
    const float* kw     = (const float*)d_in[12];

    float* out   = (float*)d_out;
    float* fullk = out + (size_t)MROWS * D_IN;
    float* fullv = fullk + (size_t)BATCH * NKV * L_FULL * HD;

    float *qraw, *kraw, *vraw, *qrot, *ctx;
    __nv_bfloat16 *x3, *w3q, *w3k, *w3v, *w3o, *ctx3;
    __half *kh, *kl, *vh, *vl;
    cudaGetSymbolAddress((void**)&qraw, g_qraw);
    cudaGetSymbolAddress((void**)&kraw, g_kraw);
    cudaGetSymbolAddress((void**)&vraw, g_vraw);
    cudaGetSymbolAddress((void**)&qrot, g_qrot);
    cudaGetSymbolAddress((void**)&ctx,  g_ctx);
    cudaGetSymbolAddress((void**)&x3,   g_x3);
    cudaGetSymbolAddress((void**)&w3q,  g_w3q);
    cudaGetSymbolAddress((void**)&w3k,  g_w3k);
    cudaGetSymbolAddress((void**)&w3v,  g_w3v);
    cudaGetSymbolAddress((void**)&w3o,  g_w3o);
    cudaGetSymbolAddress((void**)&ctx3, g_ctx3);
    cudaGetSymbolAddress((void**)&kh,   g_kh);
    cudaGetSymbolAddress((void**)&kl,   g_kl);
    cudaGetSymbolAddress((void**)&vh,   g_vh);
    cudaGetSymbolAddress((void**)&vl,   g_vl);

    cudaFuncSetAttribute(gemm_bf16, cudaFuncAttributeMaxDynamicSharedMemorySize,
                         GEMM_SMEM_BYTES);
    cudaFuncSetAttribute(attn_tc, cudaFuncAttributeMaxDynamicSharedMemorySize,
                         ATTN_SMEM_BYTES);

    // 0) split GEMM operands
    {
        int n4;
        n4 = MROWS * D_IN / 4;
        split3<<<n4 / 256, 256>>>((const float4*)x, x3, D_IN, 9, n4, 0);
        n4 = QCOLS * D_IN / 4;
        split3<<<n4 / 256, 256>>>((const float4*)Wq, w3q, D_IN, 9, n4, 1);
        n4 = KVCOLS * D_IN / 4;
        split3<<<n4 / 256, 256>>>((const float4*)Wk, w3k, D_IN, 9, n4, 1);
        split3<<<n4 / 256, 256>>>((const float4*)Wv, w3v, D_IN, 9, n4, 1);
        n4 = D_IN * QCOLS / 4;
        split3<<<n4 / 256, 256>>>((const float4*)Wo, w3o, QCOLS, 10, n4, 1);
    }

    // 1) projections
    gemm_bf16<<<dim3(QCOLS / 128, MROWS / 128), 256, GEMM_SMEM_BYTES>>>(
        x3, w3q, qraw, QCOLS, 3 * D_IN);
    gemm_bf16<<<dim3(KVCOLS / 128, MROWS / 128), 256, GEMM_SMEM_BYTES>>>(
        x3, w3k, kraw, KVCOLS, 3 * D_IN);
    gemm_bf16<<<dim3(KVCOLS / 128, MROWS / 128), 256, GEMM_SMEM_BYTES>>>(
        x3, w3v, vraw, KVCOLS, 3 * D_IN);

    // 2) norm + rope + cache assembly (+ fp16 hi/lo K/V split)
    qpost<<<MROWS * NH, 128>>>(qraw, cosb, sinb, qw, qrot);
    kvpost<<<MROWS * NKV, 128>>>(kraw, vraw, cosb, sinb, kw, fullk, fullv,
                                 kh, kl, vh, vl);
    prev_copy<<<2048, 256>>>((const float4*)prev_k, (const float4*)prev_v,
                             (float4*)fullk, (float4*)fullv,
                             (uint2*)kh, (uint2*)kl, (uint2*)vh, (uint2*)vl);

    // 3) attention -> ctx
    attn_tc<<<dim3(SEQ_T / 128, NH, BATCH), 256, ATTN_SMEM_BYTES>>>(
        qrot, kh, kl, vh, vl, ctx);

    // 4) output projection
    {
        int n4 = MROWS * QCOLS / 4;
        split3<<<n4 / 256, 256>>>((const float4*)ctx, ctx3, QCOLS, 10, n4, 0);
    }
    gemm_bf16<<<dim3(D_IN / 128, MROWS / 128), 256, GEMM_SMEM_BYTES>>>(
        ctx3, w3o, out, D_IN, 3 * QCOLS);
}